// round 3
// baseline (speedup 1.0000x reference)
#include <cuda_runtime.h>
#include <cstdint>

typedef unsigned long long ull;

#define B_ROWS 16384
#define D_DIM  1024
#define NC     65      // 64 labels + "no-label" extra column
#define CP     80      // padded classes for GEMM2 (8 warps x 10)
#define NG     37      // GEMM1 row groups
#define RPG    443     // rows per group; 37*443 = 16391 >= 16384
#define EPSV   1e-8f
#define NEGINF __int_as_float(0xff800000)

// ---------------- static device scratch (no allocations) ----------------
__device__ ull    g_mask[B_ROWS];
__device__ float  g_xninv[B_ROWS];
__device__ int    g_counts[NC];
__device__ float  g_part[NG][NC][D_DIM];    // GEMM1 partial sums (~9.9 MB)
__device__ float  g_anchorN[CP][D_DIM];     // anchor / ||anchor||, zero-padded
__device__ float  g_actInf[CP];             // 0 if active else -inf
__device__ double g_lossSum;

// ---------------- zero the loss accumulator ----------------
__global__ void k_init() { g_lossSum = 0.0; }

// ---------------- per-row label bitmask + 1/max(||x||,eps) ----------------
// labels are int32 (jax default x64-disabled demotes int64 -> int32)
__global__ void k_rows(const float* __restrict__ x, const int* __restrict__ label) {
    int warp = threadIdx.x >> 5, lane = threadIdx.x & 31;
    int row = blockIdx.x * 8 + warp;
    if (row >= B_ROWS) return;

    const float4* xr = (const float4*)(x + (size_t)row * D_DIM);
    float ss = 0.f;
#pragma unroll
    for (int k = 0; k < 8; k++) {
        float4 v = xr[lane + 32 * k];
        ss += v.x * v.x + v.y * v.y + v.z * v.z + v.w * v.w;
    }
#pragma unroll
    for (int o = 16; o; o >>= 1) ss += __shfl_xor_sync(~0u, ss, o);

    const int2* lr = (const int2*)(label + (size_t)row * 64);
    int2 lv = lr[lane];
    ull part = ((ull)(lv.x != 0) << (2 * lane)) | ((ull)(lv.y != 0) << (2 * lane + 1));
#pragma unroll
    for (int o = 16; o; o >>= 1) part |= __shfl_xor_sync(~0u, part, o);

    if (lane == 0) {
        g_mask[row]  = part;
        g_xninv[row] = 1.0f / fmaxf(sqrtf(ss), EPSV);
    }
}

// ---------------- per-class positive counts ----------------
__global__ void k_counts() {
    int c = blockIdx.x;
    int cnt = 0;
    for (int r = threadIdx.x; r < B_ROWS; r += 256) {
        ull m = g_mask[r];
        cnt += (c < 64) ? (int)((m >> c) & 1ull) : (int)(m == 0ull);
    }
    __shared__ int sred[8];
#pragma unroll
    for (int o = 16; o; o >>= 1) cnt += __shfl_xor_sync(~0u, cnt, o);
    if ((threadIdx.x & 31) == 0) sred[threadIdx.x >> 5] = cnt;
    __syncthreads();
    if (threadIdx.x == 0) {
        int t = 0;
        for (int i = 0; i < 8; i++) t += sred[i];
        g_counts[c] = t;
    }
}

// ---------------- GEMM1: partial anchor sums (lab^T @ x) ----------------
// grid (4, 37), 256 threads. Thread owns one d column, 65 register accumulators.
__global__ __launch_bounds__(256, 1) void k_gemm1(const float* __restrict__ x) {
    __shared__ float s_f[32][68];   // per-row-tile label floats (padded, 16B rows)

    int d = blockIdx.x * 256 + threadIdx.x;
    int g = blockIdx.y;
    int rbase = g * RPG;
    int rend = min(rbase + RPG, B_ROWS);

    float acc[68];
#pragma unroll
    for (int c = 0; c < 68; c++) acc[c] = 0.f;

    for (int t = 0; t * 32 < RPG; t++) {
        __syncthreads();
        for (int i = threadIdx.x; i < 32 * 68; i += 256) {
            int rr = i / 68, c = i - rr * 68;
            int r = rbase + t * 32 + rr;
            float f = 0.f;
            if (r < rend && c < 65) {
                ull m = g_mask[r];
                f = (c < 64) ? (float)((m >> c) & 1ull) : (m == 0ull ? 1.f : 0.f);
            }
            s_f[rr][c] = f;
        }
        __syncthreads();

        int rlim = rend - (rbase + t * 32);
        if (rlim > 32) rlim = 32;
        if (rlim <= 0) continue;

        const float* xp = x + (size_t)(rbase + t * 32) * D_DIM + d;
        float xv0 = xp[0];
        float xv1 = (rlim > 1) ? xp[D_DIM] : 0.f;
        for (int rr = 0; rr < rlim; rr++) {
            float xvn = (rr + 2 < rlim) ? xp[(size_t)(rr + 2) * D_DIM] : 0.f;
#pragma unroll
            for (int c4 = 0; c4 < 17; c4++) {
                float4 f4 = *(const float4*)&s_f[rr][c4 * 4];
                acc[c4 * 4 + 0] += xv0 * f4.x;
                acc[c4 * 4 + 1] += xv0 * f4.y;
                acc[c4 * 4 + 2] += xv0 * f4.z;
                acc[c4 * 4 + 3] += xv0 * f4.w;
            }
            xv0 = xv1; xv1 = xvn;
        }
    }
#pragma unroll
    for (int c = 0; c < 65; c++) g_part[g][c][d] = acc[c];
}

// ---------------- reduce partials -> normalized anchors + active mask ----------------
__global__ void k_anchor() {
    int c = blockIdx.x;
    __shared__ float sred[8];
    __shared__ float s_scale;

    if (c >= NC) {
        for (int d = threadIdx.x; d < D_DIM; d += 256) g_anchorN[c][d] = 0.f;
        if (threadIdx.x == 0) g_actInf[c] = NEGINF;
        return;
    }
    int cnt = g_counts[c];
    float inv = 1.0f / (float)max(cnt, 1);

    float a[4];
    float ss = 0.f;
#pragma unroll
    for (int k = 0; k < 4; k++) {
        int d = threadIdx.x + 256 * k;
        float s = 0.f;
        for (int g = 0; g < NG; g++) s += g_part[g][c][d];
        a[k] = s * inv;
        ss += a[k] * a[k];
    }
#pragma unroll
    for (int o = 16; o; o >>= 1) ss += __shfl_xor_sync(~0u, ss, o);
    if ((threadIdx.x & 31) == 0) sred[threadIdx.x >> 5] = ss;
    __syncthreads();
    if (threadIdx.x == 0) {
        float t = 0.f;
        for (int i = 0; i < 8; i++) t += sred[i];
        s_scale = 1.0f / fmaxf(sqrtf(t), EPSV);
        g_actInf[c] = (cnt > 0) ? 0.f : NEGINF;
    }
    __syncthreads();
    float sc = s_scale;
#pragma unroll
    for (int k = 0; k < 4; k++) g_anchorN[c][threadIdx.x + 256 * k] = a[k] * sc;
}

// ---------------- GEMM2 + fused masked log-softmax + CE ----------------
// grid 128 blocks (128 rows each), 256 threads (32 thread-rows x 8 thread-cols),
// thread tile 4 rows x 10 classes, D chunked by 32.
__global__ __launch_bounds__(256, 1) void k_gemm2(const float* __restrict__ x,
                                                  const float* __restrict__ wp,
                                                  const float* __restrict__ bp) {
    __shared__ float smem[10368];       // union: [s_x 32x132 | s_a 32x81]  /  s_dots 128x81
    __shared__ double s_loss[8];

    float* s_x = smem;                  // [32][132]
    float* s_a = smem + 32 * 132;       // [32][81]

    int tid = threadIdx.x;
    int tr = tid & 31, tc = tid >> 5;
    int rbase = blockIdx.x * 128;

    float acc[4][10];
#pragma unroll
    for (int i = 0; i < 4; i++)
#pragma unroll
        for (int j = 0; j < 10; j++) acc[i][j] = 0.f;

    for (int ch = 0; ch < 32; ch++) {
        int d0 = ch * 32;
        __syncthreads();
        // stage anchors transposed: s_a[dd][c]
        for (int i = tid; i < 2560; i += 256) {
            int c = i >> 5, dd = i & 31;
            s_a[dd * 81 + c] = g_anchorN[c][d0 + dd];
        }
        // stage x transposed: s_x[dd][rr]
#pragma unroll
        for (int p = 0; p < 4; p++) {
            int rr = p * 32 + (tid >> 3), ddq = tid & 7;
            float4 v = *(const float4*)&x[(size_t)(rbase + rr) * D_DIM + d0 + ddq * 4];
            s_x[(ddq * 4 + 0) * 132 + rr] = v.x;
            s_x[(ddq * 4 + 1) * 132 + rr] = v.y;
            s_x[(ddq * 4 + 2) * 132 + rr] = v.z;
            s_x[(ddq * 4 + 3) * 132 + rr] = v.w;
        }
        __syncthreads();
#pragma unroll 4
        for (int dd = 0; dd < 32; dd++) {
            float4 xq = *(const float4*)&s_x[dd * 132 + tr * 4];
            float av[10];
#pragma unroll
            for (int j = 0; j < 10; j++) av[j] = s_a[dd * 81 + tc * 10 + j];
#pragma unroll
            for (int j = 0; j < 10; j++) {
                acc[0][j] += xq.x * av[j];
                acc[1][j] += xq.y * av[j];
                acc[2][j] += xq.z * av[j];
                acc[3][j] += xq.w * av[j];
            }
        }
    }

    __syncthreads();
    float* s_d = smem;                  // [128][81]
#pragma unroll
    for (int i = 0; i < 4; i++)
#pragma unroll
        for (int j = 0; j < 10; j++)
            s_d[(tr * 4 + i) * 81 + (tc * 10 + j)] = acc[i][j];
    __syncthreads();

    // epilogue: warp handles 16 rows, lane covers classes {lane, lane+32, lane+64}
    float wv = *wp, bv = *bp;
    int lane = tid & 31, w = tid >> 5;
    double wl = 0.0;
    float aI0 = g_actInf[lane];
    float aI1 = g_actInf[lane + 32];
    float aI2 = (lane < 16) ? g_actInf[lane + 64] : NEGINF;

    for (int i = 0; i < 16; i++) {
        int rl = w * 16 + i;
        int rg = rbase + rl;
        float xni = g_xninv[rg];
        ull m = g_mask[rg];
        float sw = xni * wv;

        float v0 = s_d[rl * 81 + lane] * sw + bv + aI0;
        float v1 = s_d[rl * 81 + lane + 32] * sw + bv + aI1;
        float v2 = (lane < 16) ? (s_d[rl * 81 + lane + 64] * sw + bv + aI2) : NEGINF;

        float mx = fmaxf(v0, fmaxf(v1, v2));
#pragma unroll
        for (int o = 16; o; o >>= 1) mx = fmaxf(mx, __shfl_xor_sync(~0u, mx, o));

        float se = expf(v0 - mx) + expf(v1 - mx) + ((lane < 16) ? expf(v2 - mx) : 0.f);
#pragma unroll
        for (int o = 16; o; o >>= 1) se += __shfl_xor_sync(~0u, se, o);
        float lse = mx + logf(se);

        int b0 = (int)((m >> lane) & 1ull);
        int b1 = (int)((m >> (lane + 32)) & 1ull);
        int b2 = (lane == 0) ? (int)(m == 0ull) : 0;
        float sv = (b0 ? v0 : 0.f) + (b1 ? v1 : 0.f) + (b2 ? v2 : 0.f);
        int np = b0 + b1 + b2;
#pragma unroll
        for (int o = 16; o; o >>= 1) {
            sv += __shfl_xor_sync(~0u, sv, o);
            np += __shfl_xor_sync(~0u, np, o);
        }
        if (lane == 0) wl += (double)((float)np * lse - sv);
    }
    if (lane == 0) s_loss[w] = wl;
    __syncthreads();
    if (tid == 0) {
        double t = 0.0;
        for (int i = 0; i < 8; i++) t += s_loss[i];
        atomicAdd(&g_lossSum, t);
    }
}

// ---------------- finalize ----------------
__global__ void k_final(float* out) {
    if (threadIdx.x == 0) {
        long long np = 0;
        for (int c = 0; c < NC; c++) np += g_counts[c];
        out[0] = (float)(g_lossSum / (double)np);
    }
}

// ---------------- launcher ----------------
extern "C" void kernel_launch(void* const* d_in, const int* in_sizes, int n_in,
                              void* d_out, int out_size) {
    const float* x = nullptr;
    const int* label = nullptr;
    const float* wp = nullptr;
    const float* bp = nullptr;
    for (int i = 0; i < n_in; i++) {
        if (in_sizes[i] == B_ROWS * D_DIM) x = (const float*)d_in[i];
        else if (in_sizes[i] == B_ROWS * 64) label = (const int*)d_in[i];
        else if (in_sizes[i] == 1) {
            if (!wp) wp = (const float*)d_in[i];
            else bp = (const float*)d_in[i];
        }
    }
    k_init<<<1, 1>>>();
    k_rows<<<(B_ROWS + 7) / 8, 256>>>(x, label);
    k_counts<<<NC, 256>>>();
    k_gemm1<<<dim3(4, NG), 256>>>(x);
    k_anchor<<<CP, 256>>>();
    k_gemm2<<<B_ROWS / 128, 256>>>(x, wp, bp);
    k_final<<<1, 1>>>((float*)d_out);
}

// round 4
// speedup vs baseline: 1.1949x; 1.1949x over previous
#include <cuda_runtime.h>
#include <cstdint>

typedef unsigned long long ull;

#define B_ROWS 16384
#define D_DIM  1024
#define NC     65      // 64 labels + "no-label" extra column
#define CP     80      // padded classes for GEMM2 (8 warps x 10)
#define NG     37      // GEMM1 pair groups
#define NPAIRS 8192    // B_ROWS/2
#define PPG    222     // pairs per group; 37*222 = 8214 >= 8192
#define NCH    33      // classes per half (ch=0: 0..32, ch=1: 33..65 incl. pad 65)
#define EPSV   1e-8f
#define NEGINF __int_as_float(0xff800000)

// packed f32x2 fma: acc += a * b (elementwise, two independent fp32 FMAs)
#define FFMA2(acc, a, bb) asm("fma.rn.f32x2 %0, %1, %2, %0;" : "+l"(acc) : "l"(a), "l"(bb))

// ---------------- static device scratch (no allocations) ----------------
__device__ ull    g_mask[B_ROWS];
__device__ float  g_xninv[B_ROWS];
__device__ int    g_counts[NC];
__device__ float  g_part[NG][NC][D_DIM];    // GEMM1 partial sums (~9.9 MB)
__device__ float  g_anchorN[CP][D_DIM];     // anchor / ||anchor||, zero-padded
__device__ float  g_actInf[CP];             // 0 if active else -inf
__device__ double g_lossSum;

// ---------------- zero the loss accumulator ----------------
__global__ void k_init() { g_lossSum = 0.0; }

// ---------------- per-row label bitmask + 1/max(||x||,eps) ----------------
// labels are int32 (jax default x64-disabled demotes int64 -> int32)
__global__ void k_rows(const float* __restrict__ x, const int* __restrict__ label) {
    int warp = threadIdx.x >> 5, lane = threadIdx.x & 31;
    int row = blockIdx.x * 8 + warp;
    if (row >= B_ROWS) return;

    const float4* xr = (const float4*)(x + (size_t)row * D_DIM);
    float ss = 0.f;
#pragma unroll
    for (int k = 0; k < 8; k++) {
        float4 v = xr[lane + 32 * k];
        ss += v.x * v.x + v.y * v.y + v.z * v.z + v.w * v.w;
    }
#pragma unroll
    for (int o = 16; o; o >>= 1) ss += __shfl_xor_sync(~0u, ss, o);

    const int2* lr = (const int2*)(label + (size_t)row * 64);
    int2 lv = lr[lane];
    ull part = ((ull)(lv.x != 0) << (2 * lane)) | ((ull)(lv.y != 0) << (2 * lane + 1));
#pragma unroll
    for (int o = 16; o; o >>= 1) part |= __shfl_xor_sync(~0u, part, o);

    if (lane == 0) {
        g_mask[row]  = part;
        g_xninv[row] = 1.0f / fmaxf(sqrtf(ss), EPSV);
    }
}

// ---------------- per-class positive counts ----------------
__global__ void k_counts() {
    int c = blockIdx.x;
    int cnt = 0;
    for (int r = threadIdx.x; r < B_ROWS; r += 256) {
        ull m = g_mask[r];
        cnt += (c < 64) ? (int)((m >> c) & 1ull) : (int)(m == 0ull);
    }
    __shared__ int sred[8];
#pragma unroll
    for (int o = 16; o; o >>= 1) cnt += __shfl_xor_sync(~0u, cnt, o);
    if ((threadIdx.x & 31) == 0) sred[threadIdx.x >> 5] = cnt;
    __syncthreads();
    if (threadIdx.x == 0) {
        int t = 0;
        for (int i = 0; i < 8; i++) t += sred[i];
        g_counts[c] = t;
    }
}

// ---------------- GEMM1: partial anchor sums (lab^T @ x) ----------------
// grid (4 dtiles, 2 class-halves, 37 pair-groups), 256 threads, 2 CTAs/SM.
// Thread owns one d column; f32x2 packs a ROW PAIR (r0=2p, r1=2p+1).
// 34 packed accumulators (33 real classes + 1 zero pad), FFMA2 mainloop.
__global__ __launch_bounds__(256, 2) void k_gemm1(const float* __restrict__ x) {
    __shared__ __align__(16) ull s_l[32][34];   // packed (f_r0, f_r1) per (pair, classLocal)
    __shared__ ull s_m[64];                      // raw masks for the 64 rows of a tile

    const int d   = blockIdx.x * 256 + threadIdx.x;
    const int ch  = blockIdx.y;
    const int g   = blockIdx.z;
    const int tid = threadIdx.x;
    const int pbase = g * PPG;
    const int npair = min(pbase + PPG, NPAIRS) - pbase;   // 200..222

    ull acc[34];
#pragma unroll
    for (int c = 0; c < 34; c++) acc[c] = 0ull;

    // x prefetch ring, depth 4 (two LDG.32 per slot: rows 2p and 2p+1, same d)
    float fx0[4], fx1[4];
    const float* xd = x + d;
#pragma unroll
    for (int k = 0; k < 4; k++) {
        bool v = (k < npair);
        size_t r0 = (size_t)(2 * (pbase + k)) * D_DIM;
        fx0[k] = v ? xd[r0] : 0.f;
        fx1[k] = v ? xd[r0 + D_DIM] : 0.f;
    }

    const int ntiles = (npair + 31) >> 5;
    for (int t = 0; t < ntiles; t++) {
        __syncthreads();
        if (tid < 64) {
            int r = 2 * (pbase + t * 32) + tid;
            s_m[tid] = (r < B_ROWS) ? g_mask[r] : 0ull;
        }
        __syncthreads();
        // build packed label pairs from staged masks
        for (int i = tid; i < 32 * 34; i += 256) {
            int pp = i / 34, cl = i - pp * 34;
            int gp = t * 32 + pp;
            ull v = 0ull;
            if (gp < npair && cl < NCH) {
                int cg = ch * NCH + cl;
                if (cg < NC) {
                    ull m0 = s_m[2 * pp], m1 = s_m[2 * pp + 1];
                    float f0, f1;
                    if (cg < 64) {
                        f0 = (float)((m0 >> cg) & 1ull);
                        f1 = (float)((m1 >> cg) & 1ull);
                    } else {
                        f0 = (m0 == 0ull) ? 1.f : 0.f;
                        f1 = (m1 == 0ull) ? 1.f : 0.f;
                    }
                    v = (ull)__float_as_uint(f0) | ((ull)__float_as_uint(f1) << 32);
                }
            }
            s_l[pp][cl] = v;
        }
        __syncthreads();

        const int plim = min(32, npair - t * 32);
#pragma unroll 4
        for (int pp = 0; pp < plim; pp++) {
            const int idx = t * 32 + pp;
            const int slot = idx & 3;
            ull xv2 = (ull)__float_as_uint(fx0[slot]) | ((ull)__float_as_uint(fx1[slot]) << 32);
            // refill slot with pair idx+4 (x addressing independent of tiles)
            {
                int pn = idx + 4;
                bool v = (pn < npair);
                size_t r0 = (size_t)(2 * (pbase + pn)) * D_DIM;
                fx0[slot] = v ? xd[r0] : 0.f;
                fx1[slot] = v ? xd[r0 + D_DIM] : 0.f;
            }
#pragma unroll
            for (int c2 = 0; c2 < 17; c2++) {
                ulonglong2 lv = *(const ulonglong2*)&s_l[pp][c2 * 2];
                FFMA2(acc[c2 * 2 + 0], xv2, lv.x);
                FFMA2(acc[c2 * 2 + 1], xv2, lv.y);
            }
        }
    }

#pragma unroll
    for (int cl = 0; cl < NCH; cl++) {
        int cg = ch * NCH + cl;
        if (cg < NC) {
            float lo = __uint_as_float((unsigned)(acc[cl] & 0xffffffffull));
            float hi = __uint_as_float((unsigned)(acc[cl] >> 32));
            g_part[g][cg][d] = lo + hi;
        }
    }
}

// ---------------- reduce partials -> normalized anchors + active mask ----------------
__global__ void k_anchor() {
    int c = blockIdx.x;
    __shared__ float sred[8];
    __shared__ float s_scale;

    if (c >= NC) {
        for (int d = threadIdx.x; d < D_DIM; d += 256) g_anchorN[c][d] = 0.f;
        if (threadIdx.x == 0) g_actInf[c] = NEGINF;
        return;
    }
    int cnt = g_counts[c];
    float inv = 1.0f / (float)max(cnt, 1);

    float a[4];
    float ss = 0.f;
#pragma unroll
    for (int k = 0; k < 4; k++) {
        int d = threadIdx.x + 256 * k;
        float s = 0.f;
        for (int g = 0; g < NG; g++) s += g_part[g][c][d];
        a[k] = s * inv;
        ss += a[k] * a[k];
    }
#pragma unroll
    for (int o = 16; o; o >>= 1) ss += __shfl_xor_sync(~0u, ss, o);
    if ((threadIdx.x & 31) == 0) sred[threadIdx.x >> 5] = ss;
    __syncthreads();
    if (threadIdx.x == 0) {
        float t = 0.f;
        for (int i = 0; i < 8; i++) t += sred[i];
        s_scale = 1.0f / fmaxf(sqrtf(t), EPSV);
        g_actInf[c] = (cnt > 0) ? 0.f : NEGINF;
    }
    __syncthreads();
    float sc = s_scale;
#pragma unroll
    for (int k = 0; k < 4; k++) g_anchorN[c][threadIdx.x + 256 * k] = a[k] * sc;
}

// ---------------- GEMM2 + fused masked log-softmax + CE ----------------
// grid 128 blocks (128 rows each), 256 threads (32 thread-rows x 8 thread-cols),
// thread tile 4 rows x 10 classes, D chunked by 32.
__global__ __launch_bounds__(256, 1) void k_gemm2(const float* __restrict__ x,
                                                  const float* __restrict__ wp,
                                                  const float* __restrict__ bp) {
    __shared__ float smem[10368];       // union: [s_x 32x132 | s_a 32x81]  /  s_dots 128x81
    __shared__ double s_loss[8];

    float* s_x = smem;                  // [32][132]
    float* s_a = smem + 32 * 132;       // [32][81]

    int tid = threadIdx.x;
    int tr = tid & 31, tc = tid >> 5;
    int rbase = blockIdx.x * 128;

    float acc[4][10];
#pragma unroll
    for (int i = 0; i < 4; i++)
#pragma unroll
        for (int j = 0; j < 10; j++) acc[i][j] = 0.f;

    for (int ch = 0; ch < 32; ch++) {
        int d0 = ch * 32;
        __syncthreads();
        // stage anchors transposed: s_a[dd][c]
        for (int i = tid; i < 2560; i += 256) {
            int c = i >> 5, dd = i & 31;
            s_a[dd * 81 + c] = g_anchorN[c][d0 + dd];
        }
        // stage x transposed: s_x[dd][rr]
#pragma unroll
        for (int p = 0; p < 4; p++) {
            int rr = p * 32 + (tid >> 3), ddq = tid & 7;
            float4 v = *(const float4*)&x[(size_t)(rbase + rr) * D_DIM + d0 + ddq * 4];
            s_x[(ddq * 4 + 0) * 132 + rr] = v.x;
            s_x[(ddq * 4 + 1) * 132 + rr] = v.y;
            s_x[(ddq * 4 + 2) * 132 + rr] = v.z;
            s_x[(ddq * 4 + 3) * 132 + rr] = v.w;
        }
        __syncthreads();
#pragma unroll 4
        for (int dd = 0; dd < 32; dd++) {
            float4 xq = *(const float4*)&s_x[dd * 132 + tr * 4];
            float av[10];
#pragma unroll
            for (int j = 0; j < 10; j++) av[j] = s_a[dd * 81 + tc * 10 + j];
#pragma unroll
            for (int j = 0; j < 10; j++) {
                acc[0][j] += xq.x * av[j];
                acc[1][j] += xq.y * av[j];
                acc[2][j] += xq.z * av[j];
                acc[3][j] += xq.w * av[j];
            }
        }
    }

    __syncthreads();
    float* s_d = smem;                  // [128][81]
#pragma unroll
    for (int i = 0; i < 4; i++)
#pragma unroll
        for (int j = 0; j < 10; j++)
            s_d[(tr * 4 + i) * 81 + (tc * 10 + j)] = acc[i][j];
    __syncthreads();

    // epilogue: warp handles 16 rows, lane covers classes {lane, lane+32, lane+64}
    float wv = *wp, bv = *bp;
    int lane = tid & 31, w = tid >> 5;
    double wl = 0.0;
    float aI0 = g_actInf[lane];
    float aI1 = g_actInf[lane + 32];
    float aI2 = (lane < 16) ? g_actInf[lane + 64] : NEGINF;

    for (int i = 0; i < 16; i++) {
        int rl = w * 16 + i;
        int rg = rbase + rl;
        float xni = g_xninv[rg];
        ull m = g_mask[rg];
        float sw = xni * wv;

        float v0 = s_d[rl * 81 + lane] * sw + bv + aI0;
        float v1 = s_d[rl * 81 + lane + 32] * sw + bv + aI1;
        float v2 = (lane < 16) ? (s_d[rl * 81 + lane + 64] * sw + bv + aI2) : NEGINF;

        float mx = fmaxf(v0, fmaxf(v1, v2));
#pragma unroll
        for (int o = 16; o; o >>= 1) mx = fmaxf(mx, __shfl_xor_sync(~0u, mx, o));

        float se = expf(v0 - mx) + expf(v1 - mx) + ((lane < 16) ? expf(v2 - mx) : 0.f);
#pragma unroll
        for (int o = 16; o; o >>= 1) se += __shfl_xor_sync(~0u, se, o);
        float lse = mx + logf(se);

        int b0 = (int)((m >> lane) & 1ull);
        int b1 = (int)((m >> (lane + 32)) & 1ull);
        int b2 = (lane == 0) ? (int)(m == 0ull) : 0;
        float sv = (b0 ? v0 : 0.f) + (b1 ? v1 : 0.f) + (b2 ? v2 : 0.f);
        int np = b0 + b1 + b2;
#pragma unroll
        for (int o = 16; o; o >>= 1) {
            sv += __shfl_xor_sync(~0u, sv, o);
            np += __shfl_xor_sync(~0u, np, o);
        }
        if (lane == 0) wl += (double)((float)np * lse - sv);
    }
    if (lane == 0) s_loss[w] = wl;
    __syncthreads();
    if (tid == 0) {
        double t = 0.0;
        for (int i = 0; i < 8; i++) t += s_loss[i];
        atomicAdd(&g_lossSum, t);
    }
}

// ---------------- finalize ----------------
__global__ void k_final(float* out) {
    if (threadIdx.x == 0) {
        long long np = 0;
        for (int c = 0; c < NC; c++) np += g_counts[c];
        out[0] = (float)(g_lossSum / (double)np);
    }
}

// ---------------- launcher ----------------
extern "C" void kernel_launch(void* const* d_in, const int* in_sizes, int n_in,
                              void* d_out, int out_size) {
    const float* x = nullptr;
    const int* label = nullptr;
    const float* wp = nullptr;
    const float* bp = nullptr;
    for (int i = 0; i < n_in; i++) {
        if (in_sizes[i] == B_ROWS * D_DIM) x = (const float*)d_in[i];
        else if (in_sizes[i] == B_ROWS * 64) label = (const int*)d_in[i];
        else if (in_sizes[i] == 1) {
            if (!wp) wp = (const float*)d_in[i];
            else bp = (const float*)d_in[i];
        }
    }
    k_init<<<1, 1>>>();
    k_rows<<<(B_ROWS + 7) / 8, 256>>>(x, label);
    k_counts<<<NC, 256>>>();
    k_gemm1<<<dim3(4, 2, NG), 256>>>(x);
    k_anchor<<<CP, 256>>>();
    k_gemm2<<<B_ROWS / 128, 256>>>(x, wp, bp);
    k_final<<<1, 1>>>((float*)d_out);
}

// round 5
// speedup vs baseline: 1.2393x; 1.0371x over previous
#include <cuda_runtime.h>
#include <cstdint>

typedef unsigned long long ull;

#define B_ROWS 16384
#define D_DIM  1024
#define NC     65      // 64 labels + "no-label" extra column
#define CP     80      // padded classes for GEMM2 (8 warps x 10)
#define NG     37      // GEMM1 pair groups
#define NPAIRS 8192    // B_ROWS/2
#define PPAD   8224    // padded pairs (copy overrun safety)
#define PPG    222     // pairs per group; 37*222 = 8214 >= 8192
#define NCH    33      // classes per half (ch=0: 0..32, ch=1: 33..65 incl. pad)
#define EPSV   1e-8f
#define NEGINF __int_as_float(0xff800000)

// packed f32x2 fma: acc += a * b (two independent fp32 FMAs)
#define FFMA2(acc, a, bb) asm("fma.rn.f32x2 %0, %1, %2, %0;" : "+l"(acc) : "l"(a), "l"(bb))
#define DUP2(dst, s)      asm("mov.b64 %0, {%1, %1};" : "=l"(dst) : "r"(s))
#define UNPK2(lo, hi, s)  asm("mov.b64 {%0, %1}, %2;" : "=r"(lo), "=r"(hi) : "l"(s))

// ---------------- static device scratch (no allocations) ----------------
__device__ ull    g_mask[B_ROWS];
__device__ float  g_xninv[B_ROWS];
__device__ int    g_counts[NC];
__device__ ull    g_labp[2][PPAD][34];      // packed (f_r0,f_r1) per (half, pair, classLocal)
__device__ float  g_part[NG][NC][D_DIM];    // GEMM1 partial sums (~9.9 MB)
__device__ ull    g_anchorP[40][D_DIM];     // packed (aN[2j][d], aN[2j+1][d])
__device__ float  g_actInf[CP];             // 0 if active else -inf
__device__ double g_lossSum;

// ---------------- zero the loss accumulator ----------------
__global__ void k_init() { g_lossSum = 0.0; }

// ---------------- per-row label bitmask + 1/max(||x||,eps) ----------------
// labels are int32 (jax default x64-disabled demotes int64 -> int32)
__global__ void k_rows(const float* __restrict__ x, const int* __restrict__ label) {
    int warp = threadIdx.x >> 5, lane = threadIdx.x & 31;
    int row = blockIdx.x * 8 + warp;
    if (row >= B_ROWS) return;

    const float4* xr = (const float4*)(x + (size_t)row * D_DIM);
    float ss = 0.f;
#pragma unroll
    for (int k = 0; k < 8; k++) {
        float4 v = xr[lane + 32 * k];
        ss += v.x * v.x + v.y * v.y + v.z * v.z + v.w * v.w;
    }
#pragma unroll
    for (int o = 16; o; o >>= 1) ss += __shfl_xor_sync(~0u, ss, o);

    const int2* lr = (const int2*)(label + (size_t)row * 64);
    int2 lv = lr[lane];
    ull part = ((ull)(lv.x != 0) << (2 * lane)) | ((ull)(lv.y != 0) << (2 * lane + 1));
#pragma unroll
    for (int o = 16; o; o >>= 1) part |= __shfl_xor_sync(~0u, part, o);

    if (lane == 0) {
        g_mask[row]  = part;
        g_xninv[row] = 1.0f / fmaxf(sqrtf(ss), EPSV);
    }
}

// ---------------- pre-pack label float pairs ----------------
// one warp per pair; writes g_labp[2][p][34]
__global__ void k_pack() {
    int p = blockIdx.x * 8 + (threadIdx.x >> 5);
    int lane = threadIdx.x & 31;
    if (p >= NPAIRS) return;
    ull m0 = g_mask[2 * p], m1 = g_mask[2 * p + 1];
#pragma unroll
    for (int i = lane; i < 68; i += 32) {
        int ch = (i >= 34) ? 1 : 0;
        int cl = i - ch * 34;
        ull v = 0ull;
        if (cl < NCH) {
            int cg = ch * NCH + cl;
            if (cg < NC) {
                float f0, f1;
                if (cg < 64) {
                    f0 = (float)((m0 >> cg) & 1ull);
                    f1 = (float)((m1 >> cg) & 1ull);
                } else {
                    f0 = (m0 == 0ull) ? 1.f : 0.f;
                    f1 = (m1 == 0ull) ? 1.f : 0.f;
                }
                v = (ull)__float_as_uint(f0) | ((ull)__float_as_uint(f1) << 32);
            }
        }
        g_labp[ch][p][cl] = v;
    }
}

// ---------------- per-class positive counts ----------------
__global__ void k_counts() {
    int c = blockIdx.x;
    int cnt = 0;
    for (int r = threadIdx.x; r < B_ROWS; r += 256) {
        ull m = g_mask[r];
        cnt += (c < 64) ? (int)((m >> c) & 1ull) : (int)(m == 0ull);
    }
    __shared__ int sred[8];
#pragma unroll
    for (int o = 16; o; o >>= 1) cnt += __shfl_xor_sync(~0u, cnt, o);
    if ((threadIdx.x & 31) == 0) sred[threadIdx.x >> 5] = cnt;
    __syncthreads();
    if (threadIdx.x == 0) {
        int t = 0;
        for (int i = 0; i < 8; i++) t += sred[i];
        g_counts[c] = t;
    }
}

// ---------------- GEMM1: partial anchor sums (lab^T @ x) ----------------
// grid (4 dtiles, 2 class-halves, 37 pair-groups), 256 threads, 2 CTAs/SM.
// Thread owns one d column; f32x2 packs a ROW PAIR. FFMA2 mainloop.
__global__ __launch_bounds__(256, 2) void k_gemm1(const float* __restrict__ x) {
    __shared__ __align__(16) ull s_l[32][34];   // packed label pairs for a 32-pair tile

    const int d   = blockIdx.x * 256 + threadIdx.x;
    const int ch  = blockIdx.y;
    const int g   = blockIdx.z;
    const int tid = threadIdx.x;
    const int pbase = g * PPG;
    const int npair = min(pbase + PPG, NPAIRS) - pbase;

    ull acc[34];
#pragma unroll
    for (int c = 0; c < 34; c++) acc[c] = 0ull;

    // x prefetch ring, depth 4
    float fx0[4], fx1[4];
    const float* xd = x + d;
#pragma unroll
    for (int k = 0; k < 4; k++) {
        bool v = (k < npair);
        size_t r0 = (size_t)(2 * (pbase + k)) * D_DIM;
        fx0[k] = v ? xd[r0] : 0.f;
        fx1[k] = v ? xd[r0 + D_DIM] : 0.f;
    }

    const int ntiles = (npair + 31) >> 5;
    for (int t = 0; t < ntiles; t++) {
        __syncthreads();
        {   // raw 16B copy of the pre-packed tile (32*34*8 = 8704 B = 544 x 16B)
            const float4* src = (const float4*)&g_labp[ch][pbase + t * 32][0];
            float4* dst = (float4*)&s_l[0][0];
            for (int i = tid; i < 544; i += 256) dst[i] = src[i];
        }
        __syncthreads();

        const int plim = min(32, npair - t * 32);
#pragma unroll 4
        for (int pp = 0; pp < plim; pp++) {
            const int idx = t * 32 + pp;
            const int slot = idx & 3;
            ull xv2 = (ull)__float_as_uint(fx0[slot]) | ((ull)__float_as_uint(fx1[slot]) << 32);
            {   // refill slot with pair idx+4
                int pn = idx + 4;
                bool v = (pn < npair);
                size_t r0 = (size_t)(2 * (pbase + pn)) * D_DIM;
                fx0[slot] = v ? xd[r0] : 0.f;
                fx1[slot] = v ? xd[r0 + D_DIM] : 0.f;
            }
#pragma unroll
            for (int c2 = 0; c2 < 17; c2++) {
                ulonglong2 lv = *(const ulonglong2*)&s_l[pp][c2 * 2];
                FFMA2(acc[c2 * 2 + 0], xv2, lv.x);
                FFMA2(acc[c2 * 2 + 1], xv2, lv.y);
            }
        }
    }

#pragma unroll
    for (int cl = 0; cl < NCH; cl++) {
        int cg = ch * NCH + cl;
        if (cg < NC) {
            float lo = __uint_as_float((unsigned)(acc[cl] & 0xffffffffull));
            float hi = __uint_as_float((unsigned)(acc[cl] >> 32));
            g_part[g][cg][d] = lo + hi;
        }
    }
}

// ---------------- reduce partials -> normalized packed anchors + active mask ----------------
__global__ void k_anchor() {
    int c = blockIdx.x;
    __shared__ float sred[8];
    __shared__ float s_scale;
    float* aP = (float*)g_anchorP;   // [40][1024][2] float view

    if (c >= NC) {
        for (int d = threadIdx.x; d < D_DIM; d += 256)
            aP[(size_t)(c >> 1) * 2048 + d * 2 + (c & 1)] = 0.f;
        if (threadIdx.x == 0) g_actInf[c] = NEGINF;
        return;
    }
    int cnt = g_counts[c];
    float inv = 1.0f / (float)max(cnt, 1);

    float a[4];
    float ss = 0.f;
#pragma unroll
    for (int k = 0; k < 4; k++) {
        int d = threadIdx.x + 256 * k;
        float s = 0.f;
        for (int g = 0; g < NG; g++) s += g_part[g][c][d];
        a[k] = s * inv;
        ss += a[k] * a[k];
    }
#pragma unroll
    for (int o = 16; o; o >>= 1) ss += __shfl_xor_sync(~0u, ss, o);
    if ((threadIdx.x & 31) == 0) sred[threadIdx.x >> 5] = ss;
    __syncthreads();
    if (threadIdx.x == 0) {
        float t = 0.f;
        for (int i = 0; i < 8; i++) t += sred[i];
        s_scale = 1.0f / fmaxf(sqrtf(t), EPSV);
        g_actInf[c] = (cnt > 0) ? 0.f : NEGINF;
    }
    __syncthreads();
    float sc = s_scale;
#pragma unroll
    for (int k = 0; k < 4; k++) {
        int d = threadIdx.x + 256 * k;
        aP[(size_t)(c >> 1) * 2048 + d * 2 + (c & 1)] = a[k] * sc;
    }
}

// ---------------- GEMM2 + fused masked log-softmax + CE ----------------
// grid 128 blocks (128 rows each), 512 threads (64 thread-rows x 8 thread-cols),
// thread tile 2 rows x 5 class-pairs (f32x2 packs class pairs), D chunked by 32.
__global__ __launch_bounds__(512, 1) void k_gemm2(const float* __restrict__ x,
                                                  const float* __restrict__ wp,
                                                  const float* __restrict__ bp) {
    __shared__ float smem[10368];       // union: [s_x 32x132 | s_a 32x41 ull] / s_d 128x81
    __shared__ double s_loss[16];

    float* s_x = smem;                          // [32][132] floats
    ull*   s_a = (ull*)(smem + 4224);           // [32][41] ull (16896B offset, 8B aligned)

    int tid = threadIdx.x;
    int tr = tid & 63, tc = tid >> 6;           // 64 rows-of-2 x 8 class-groups
    int rbase = blockIdx.x * 128;

    ull acc[2][5];
#pragma unroll
    for (int i = 0; i < 2; i++)
#pragma unroll
        for (int j = 0; j < 5; j++) acc[i][j] = 0ull;

    for (int chk = 0; chk < 32; chk++) {
        int d0 = chk * 32;
        __syncthreads();
        // stage packed anchors: s_a[dd][j] = g_anchorP[j][d0+dd]
        for (int i = tid; i < 1280; i += 512) {
            int dd = i & 31, j = i >> 5;
            s_a[dd * 41 + j] = g_anchorP[j][d0 + dd];
        }
        // stage x transposed: s_x[dd][rr]
#pragma unroll
        for (int p = 0; p < 2; p++) {
            int rr = p * 64 + (tid >> 3), ddq = tid & 7;
            float4 v = *(const float4*)&x[(size_t)(rbase + rr) * D_DIM + d0 + ddq * 4];
            s_x[(ddq * 4 + 0) * 132 + rr] = v.x;
            s_x[(ddq * 4 + 1) * 132 + rr] = v.y;
            s_x[(ddq * 4 + 2) * 132 + rr] = v.z;
            s_x[(ddq * 4 + 3) * 132 + rr] = v.w;
        }
        __syncthreads();
#pragma unroll 4
        for (int dd = 0; dd < 32; dd++) {
            uint2 xp = *(const uint2*)&s_x[dd * 132 + tr * 2];   // rows 2tr, 2tr+1
            ull xa, xb;
            DUP2(xa, xp.x);
            DUP2(xb, xp.y);
            const ull* ap = &s_a[dd * 41 + tc * 5];
#pragma unroll
            for (int j = 0; j < 5; j++) {
                ull av = ap[j];
                FFMA2(acc[0][j], xa, av);
                FFMA2(acc[1][j], xb, av);
            }
        }
    }

    __syncthreads();
    float* s_d = smem;                  // [128][81]
#pragma unroll
    for (int i = 0; i < 2; i++) {
        int r = tr * 2 + i;
#pragma unroll
        for (int j = 0; j < 5; j++) {
            unsigned lo, hi;
            UNPK2(lo, hi, acc[i][j]);
            s_d[r * 81 + tc * 10 + 2 * j]     = __uint_as_float(lo);
            s_d[r * 81 + tc * 10 + 2 * j + 1] = __uint_as_float(hi);
        }
    }
    __syncthreads();

    // epilogue: 16 warps x 8 rows; lane covers classes {lane, lane+32, lane+64}
    float wv = *wp, bv = *bp;
    int lane = tid & 31, w = tid >> 5;
    double wl = 0.0;
    float aI0 = g_actInf[lane];
    float aI1 = g_actInf[lane + 32];
    float aI2 = (lane < 16) ? g_actInf[lane + 64] : NEGINF;

    for (int i = 0; i < 8; i++) {
        int rl = w * 8 + i;
        int rg = rbase + rl;
        float xni = g_xninv[rg];
        ull m = g_mask[rg];
        float sw = xni * wv;

        float v0 = s_d[rl * 81 + lane] * sw + bv + aI0;
        float v1 = s_d[rl * 81 + lane + 32] * sw + bv + aI1;
        float v2 = (lane < 16) ? (s_d[rl * 81 + lane + 64] * sw + bv + aI2) : NEGINF;

        float mx = fmaxf(v0, fmaxf(v1, v2));
#pragma unroll
        for (int o = 16; o; o >>= 1) mx = fmaxf(mx, __shfl_xor_sync(~0u, mx, o));

        float se = expf(v0 - mx) + expf(v1 - mx) + ((lane < 16) ? expf(v2 - mx) : 0.f);
#pragma unroll
        for (int o = 16; o; o >>= 1) se += __shfl_xor_sync(~0u, se, o);
        float lse = mx + logf(se);

        int b0 = (int)((m >> lane) & 1ull);
        int b1 = (int)((m >> (lane + 32)) & 1ull);
        int b2 = (lane == 0) ? (int)(m == 0ull) : 0;
        float sv = (b0 ? v0 : 0.f) + (b1 ? v1 : 0.f) + (b2 ? v2 : 0.f);
        int np = b0 + b1 + b2;
#pragma unroll
        for (int o = 16; o; o >>= 1) {
            sv += __shfl_xor_sync(~0u, sv, o);
            np += __shfl_xor_sync(~0u, np, o);
        }
        if (lane == 0) wl += (double)((float)np * lse - sv);
    }
    if (lane == 0) s_loss[w] = wl;
    __syncthreads();
    if (tid == 0) {
        double t = 0.0;
        for (int i = 0; i < 16; i++) t += s_loss[i];
        atomicAdd(&g_lossSum, t);
    }
}

// ---------------- finalize ----------------
__global__ void k_final(float* out) {
    if (threadIdx.x == 0) {
        long long np = 0;
        for (int c = 0; c < NC; c++) np += g_counts[c];
        out[0] = (float)(g_lossSum / (double)np);
    }
}

// ---------------- launcher ----------------
extern "C" void kernel_launch(void* const* d_in, const int* in_sizes, int n_in,
                              void* d_out, int out_size) {
    const float* x = nullptr;
    const int* label = nullptr;
    const float* wp = nullptr;
    const float* bp = nullptr;
    for (int i = 0; i < n_in; i++) {
        if (in_sizes[i] == B_ROWS * D_DIM) x = (const float*)d_in[i];
        else if (in_sizes[i] == B_ROWS * 64) label = (const int*)d_in[i];
        else if (in_sizes[i] == 1) {
            if (!wp) wp = (const float*)d_in[i];
            else bp = (const float*)d_in[i];
        }
    }
    k_init<<<1, 1>>>();
    k_rows<<<(B_ROWS + 7) / 8, 256>>>(x, label);
    k_pack<<<NPAIRS / 8, 256>>>();
    k_counts<<<NC, 256>>>();
    k_gemm1<<<dim3(4, 2, NG), 256>>>(x);
    k_anchor<<<CP, 256>>>();
    k_gemm2<<<B_ROWS / 128, 512>>>(x, wp, bp);
    k_final<<<1, 1>>>((float*)d_out);
}

// round 6
// speedup vs baseline: 1.2416x; 1.0019x over previous
#include <cuda_runtime.h>
#include <cstdint>

typedef unsigned long long ull;

#define B_ROWS 16384
#define D_DIM  1024
#define NC     65      // 64 labels + "no-label" extra column
#define CP     80      // padded classes (8 tc groups x 10)
#define NG     37      // GEMM1 pair groups
#define NPAIRS 8192    // B_ROWS/2
#define PPAD   8224    // padded pairs (tile copy overrun safety)
#define PPG    222     // pairs per group; 37*222 = 8214 >= 8192
#define NCH1   17      // classes per quarter (4*17=68 >= 65)
#define EPSV   1e-8f
#define NEGINF __int_as_float(0xff800000)

// packed f32x2 fma: acc += a * b (two independent fp32 FMAs)
#define FFMA2(acc, a, bb) asm("fma.rn.f32x2 %0, %1, %2, %0;" : "+l"(acc) : "l"(a), "l"(bb))
#define PK2(dst, lo, hi)  asm("mov.b64 %0, {%1, %2};" : "=l"(dst) : "f"(lo), "f"(hi))
#define DUP2(dst, s)      asm("mov.b64 %0, {%1, %1};" : "=l"(dst) : "f"(s))
#define UNPK2(lo, hi, s)  asm("mov.b64 {%0, %1}, %2;" : "=f"(lo), "=f"(hi) : "l"(s))

// ---------------- static device scratch (no allocations) ----------------
__device__ ull    g_mask[B_ROWS];
__device__ float  g_xninv[B_ROWS];
__device__ int    g_cntp[64][65];           // per-metablock partial counts
__device__ __align__(16) ull g_labp[4][PPAD][18];  // packed (f_r0,f_r1) per (quarter, pair, cl)
__device__ float  g_part[NG][68][D_DIM];    // GEMM1 partial sums
__device__ ull    g_anchorP[40][D_DIM];     // packed (aN[2j][d], aN[2j+1][d])
__device__ float  g_actInf[CP];             // 0 if active else -inf
__device__ ull    g_dotsP[2][B_ROWS][40];   // partial dot products (2 D-halves)
__device__ double g_lossSum;

// ---------------- per-row label bitmask + 1/max(||x||,eps) ----------------
__global__ void k_rows(const float* __restrict__ x, const int* __restrict__ label) {
    int warp = threadIdx.x >> 5, lane = threadIdx.x & 31;
    int row = blockIdx.x * 8 + warp;
    if (row >= B_ROWS) return;

    const float4* xr = (const float4*)(x + (size_t)row * D_DIM);
    float ss = 0.f;
#pragma unroll
    for (int k = 0; k < 8; k++) {
        float4 v = xr[lane + 32 * k];
        ss += v.x * v.x + v.y * v.y + v.z * v.z + v.w * v.w;
    }
#pragma unroll
    for (int o = 16; o; o >>= 1) ss += __shfl_xor_sync(~0u, ss, o);

    const int2* lr = (const int2*)(label + (size_t)row * 64);
    int2 lv = lr[lane];
    ull part = ((ull)(lv.x != 0) << (2 * lane)) | ((ull)(lv.y != 0) << (2 * lane + 1));
#pragma unroll
    for (int o = 16; o; o >>= 1) part |= __shfl_xor_sync(~0u, part, o);

    if (lane == 0) {
        g_mask[row]  = part;
        g_xninv[row] = 1.0f / fmaxf(sqrtf(ss), EPSV);
    }
}

// ---------------- meta: partial counts (ballot) + label pair packing + loss zero ----------------
// 64 blocks x 256 threads; block covers 256 rows = 128 pairs
__global__ void k_meta() {
    __shared__ ull s_m[256];
    __shared__ int s_cnt[65];
    int tid = threadIdx.x, b = blockIdx.x, lane = tid & 31;
    int row = b * 256 + tid;
    ull m = g_mask[row];
    s_m[tid] = m;
    if (tid < 65) s_cnt[tid] = 0;
    __syncthreads();

    int ca = 0, cb = 0, cz = 0;
#pragma unroll
    for (int c = 0; c < 32; c++) {
        unsigned bal = __ballot_sync(~0u, (int)((m >> c) & 1ull));
        if (lane == c) ca = __popc(bal);
    }
#pragma unroll
    for (int c = 32; c < 64; c++) {
        unsigned bal = __ballot_sync(~0u, (int)((m >> c) & 1ull));
        if (lane == c - 32) cb = __popc(bal);
    }
    {
        unsigned bal = __ballot_sync(~0u, m == 0ull);
        if (lane == 0) cz = __popc(bal);
    }
    atomicAdd(&s_cnt[lane], ca);
    atomicAdd(&s_cnt[lane + 32], cb);
    if (lane == 0) atomicAdd(&s_cnt[64], cz);

    // pack: thread owns pair p = tid>>1, quarters {0,1} or {2,3} by tid&1
    int p = tid >> 1;
    ull m0 = s_m[2 * p], m1 = s_m[2 * p + 1];
    int pg = b * 128 + p;
#pragma unroll
    for (int qq = 0; qq < 2; qq++) {
        int q = 2 * (tid & 1) + qq;
#pragma unroll
        for (int cl = 0; cl < 18; cl++) {
            int cg = q * NCH1 + cl;
            ull v = 0ull;
            if (cl < NCH1 && cg < NC) {
                float f0, f1;
                if (cg < 64) {
                    f0 = (float)((m0 >> cg) & 1ull);
                    f1 = (float)((m1 >> cg) & 1ull);
                } else {
                    f0 = (m0 == 0ull) ? 1.f : 0.f;
                    f1 = (m1 == 0ull) ? 1.f : 0.f;
                }
                v = (ull)__float_as_uint(f0) | ((ull)__float_as_uint(f1) << 32);
            }
            g_labp[q][pg][cl] = v;
        }
    }
    __syncthreads();
    if (tid < 65) g_cntp[b][tid] = s_cnt[tid];
    if (b == 0 && tid == 0) g_lossSum = 0.0;
}

// ---------------- GEMM1: partial anchor sums (lab^T @ x) ----------------
// grid (2 dtiles, 4 quarters, 37 groups) = 296 blocks, 256 threads, 2 CTAs/SM.
// Thread owns TWO d columns (d, d+256); f32x2 packs a ROW PAIR; label LDS
// feeds 4 FFMA2 per 16B -> FMA-pipe bound.
__global__ __launch_bounds__(256, 2) void k_gemm1(const float* __restrict__ x) {
    __shared__ __align__(16) ull s_l[32][18];

    const int tid = threadIdx.x;
    const int d0  = blockIdx.x * 512 + tid;
    const int q   = blockIdx.y;
    const int g   = blockIdx.z;
    const int pbase = g * PPG;
    const int npair = min(pbase + PPG, NPAIRS) - pbase;

    ull acc[2][17];
#pragma unroll
    for (int j = 0; j < 2; j++)
#pragma unroll
        for (int c = 0; c < 17; c++) acc[j][c] = 0ull;

    const float* xa = x + d0;
    const float* xb = x + d0 + 256;
    float f0a[2], f1a[2], f0b[2], f1b[2];   // prefetch ring depth 2
#pragma unroll
    for (int k = 0; k < 2; k++) {
        size_t r = (size_t)(2 * (pbase + k)) * D_DIM;
        f0a[k] = xa[r]; f1a[k] = xa[r + D_DIM];
        f0b[k] = xb[r]; f1b[k] = xb[r + D_DIM];
    }

    const int ntiles = (npair + 31) >> 5;
    for (int t = 0; t < ntiles; t++) {
        __syncthreads();
        {   // raw 16B copy of the pre-packed tile: 32*18 ull = 288 float4
            const float4* src = (const float4*)&g_labp[q][pbase + t * 32][0];
            float4* dst = (float4*)s_l;
            dst[tid] = src[tid];
            if (tid < 32) dst[256 + tid] = src[256 + tid];
        }
        __syncthreads();

        const int plim = min(32, npair - t * 32);
#pragma unroll 4
        for (int pp = 0; pp < plim; pp++) {
            const int idx = t * 32 + pp;
            const int sl = idx & 1;
            ull xva, xvb;
            PK2(xva, f0a[sl], f1a[sl]);
            PK2(xvb, f0b[sl], f1b[sl]);
            int pn = idx + 2;
            if (pn < npair) {
                size_t r = (size_t)(2 * (pbase + pn)) * D_DIM;
                f0a[sl] = xa[r]; f1a[sl] = xa[r + D_DIM];
                f0b[sl] = xb[r]; f1b[sl] = xb[r + D_DIM];
            }
#pragma unroll
            for (int c2 = 0; c2 < 8; c2++) {
                ulonglong2 lv = *(const ulonglong2*)&s_l[pp][2 * c2];
                FFMA2(acc[0][2 * c2],     xva, lv.x);
                FFMA2(acc[1][2 * c2],     xvb, lv.x);
                FFMA2(acc[0][2 * c2 + 1], xva, lv.y);
                FFMA2(acc[1][2 * c2 + 1], xvb, lv.y);
            }
            ull lv16 = s_l[pp][16];
            FFMA2(acc[0][16], xva, lv16);
            FFMA2(acc[1][16], xvb, lv16);
        }
    }

#pragma unroll
    for (int cl = 0; cl < 17; cl++) {
        int c = q * NCH1 + cl;
        if (c < NC) {
            float lo, hi;
            UNPK2(lo, hi, acc[0][cl]);
            g_part[g][c][d0] = lo + hi;
            UNPK2(lo, hi, acc[1][cl]);
            g_part[g][c][d0 + 256] = lo + hi;
        }
    }
}

// ---------------- reduce partials -> normalized packed anchors + active mask ----------------
__global__ void k_anchor() {
    int c = blockIdx.x;
    __shared__ float sred[8];
    __shared__ float s_scale;
    __shared__ int s_count;
    float* aP = (float*)g_anchorP;   // [40][1024][2] float view

    if (c >= NC) {
        for (int d = threadIdx.x; d < D_DIM; d += 256)
            aP[(size_t)(c >> 1) * 2048 + d * 2 + (c & 1)] = 0.f;
        if (threadIdx.x == 0) g_actInf[c] = NEGINF;
        return;
    }
    if (threadIdx.x == 0) {
        int t = 0;
#pragma unroll
        for (int b = 0; b < 64; b++) t += g_cntp[b][c];
        s_count = t;
    }
    __syncthreads();
    int cnt = s_count;
    float inv = 1.0f / (float)max(cnt, 1);

    float a[4];
    float ss = 0.f;
#pragma unroll
    for (int k = 0; k < 4; k++) {
        int d = threadIdx.x + 256 * k;
        float s = 0.f;
        for (int g = 0; g < NG; g++) s += g_part[g][c][d];
        a[k] = s * inv;
        ss += a[k] * a[k];
    }
#pragma unroll
    for (int o = 16; o; o >>= 1) ss += __shfl_xor_sync(~0u, ss, o);
    if ((threadIdx.x & 31) == 0) sred[threadIdx.x >> 5] = ss;
    __syncthreads();
    if (threadIdx.x == 0) {
        float t = 0.f;
        for (int i = 0; i < 8; i++) t += sred[i];
        s_scale = 1.0f / fmaxf(sqrtf(t), EPSV);
        g_actInf[c] = (cnt > 0) ? 0.f : NEGINF;
    }
    __syncthreads();
    float sc = s_scale;
#pragma unroll
    for (int k = 0; k < 4; k++) {
        int d = threadIdx.x + 256 * k;
        aP[(size_t)(c >> 1) * 2048 + d * 2 + (c & 1)] = a[k] * sc;
    }
}

// ---------------- GEMM2: x @ anchorN^T, partial over D-halves ----------------
// grid (128 rowblocks, 2 D-halves), 256 threads (32 tr x 8 tc), 2 CTAs/SM.
// Thread tile 4 rows x 5 class-pairs (f32x2 packs class pairs).
__global__ __launch_bounds__(256, 2) void k_gemm2(const float* __restrict__ x) {
    __shared__ float s_x[32 * 132];
    __shared__ __align__(16) ull s_a[32 * 48];

    int tid = threadIdx.x;
    int tr = tid & 31, tc = tid >> 5;
    int rbase = blockIdx.x * 128;
    int dbase = blockIdx.y * 512;

    ull acc[4][5];
#pragma unroll
    for (int i = 0; i < 4; i++)
#pragma unroll
        for (int j = 0; j < 5; j++) acc[i][j] = 0ull;

    for (int chk = 0; chk < 16; chk++) {
        int d0 = dbase + chk * 32;
        __syncthreads();
        // stage packed anchors into padded 6-ull tc slots
        for (int i = tid; i < 1280; i += 256) {
            int dd = i & 31, j = i >> 5;
            s_a[dd * 48 + (j / 5) * 6 + (j % 5)] = g_anchorP[j][d0 + dd];
        }
        // stage x transposed: s_x[dd][rr]
#pragma unroll
        for (int it = 0; it < 4; it++) {
            int rr = it * 32 + (tid >> 3), ddq = tid & 7;
            float4 v = *(const float4*)&x[(size_t)(rbase + rr) * D_DIM + d0 + ddq * 4];
            s_x[(ddq * 4 + 0) * 132 + rr] = v.x;
            s_x[(ddq * 4 + 1) * 132 + rr] = v.y;
            s_x[(ddq * 4 + 2) * 132 + rr] = v.z;
            s_x[(ddq * 4 + 3) * 132 + rr] = v.w;
        }
        __syncthreads();
#pragma unroll 4
        for (int dd = 0; dd < 32; dd++) {
            float4 xq = *(const float4*)&s_x[dd * 132 + tr * 4];
            ull x0, x1, x2, x3;
            DUP2(x0, xq.x); DUP2(x1, xq.y); DUP2(x2, xq.z); DUP2(x3, xq.w);
            const ull* ap = &s_a[dd * 48 + tc * 6];
            ulonglong2 a01 = *(const ulonglong2*)&ap[0];
            ulonglong2 a23 = *(const ulonglong2*)&ap[2];
            ull a4 = ap[4];
            FFMA2(acc[0][0], x0, a01.x); FFMA2(acc[1][0], x1, a01.x);
            FFMA2(acc[2][0], x2, a01.x); FFMA2(acc[3][0], x3, a01.x);
            FFMA2(acc[0][1], x0, a01.y); FFMA2(acc[1][1], x1, a01.y);
            FFMA2(acc[2][1], x2, a01.y); FFMA2(acc[3][1], x3, a01.y);
            FFMA2(acc[0][2], x0, a23.x); FFMA2(acc[1][2], x1, a23.x);
            FFMA2(acc[2][2], x2, a23.x); FFMA2(acc[3][2], x3, a23.x);
            FFMA2(acc[0][3], x0, a23.y); FFMA2(acc[1][3], x1, a23.y);
            FFMA2(acc[2][3], x2, a23.y); FFMA2(acc[3][3], x3, a23.y);
            FFMA2(acc[0][4], x0, a4);    FFMA2(acc[1][4], x1, a4);
            FFMA2(acc[2][4], x2, a4);    FFMA2(acc[3][4], x3, a4);
        }
    }

    int dh = blockIdx.y;
#pragma unroll
    for (int i = 0; i < 4; i++)
#pragma unroll
        for (int j = 0; j < 5; j++)
            g_dotsP[dh][rbase + tr * 4 + i][tc * 5 + j] = acc[i][j];
}

// ---------------- epilogue: masked log-softmax + pair-weighted CE ----------------
// grid 128 x 256 threads; warp handles 16 rows; lane covers {lane, lane+32, lane+64}
__global__ void k_epi(const float* __restrict__ wp, const float* __restrict__ bp) {
    __shared__ double s_loss[8];
    const float* dF0 = (const float*)&g_dotsP[0][0][0];
    const float* dF1 = (const float*)&g_dotsP[1][0][0];

    float wv = *wp, bv = *bp;
    int tid = threadIdx.x, lane = tid & 31, w = tid >> 5;
    int rbase = blockIdx.x * 128;
    double wl = 0.0;
    float aI0 = g_actInf[lane];
    float aI1 = g_actInf[lane + 32];
    float aI2 = (lane < 16) ? g_actInf[lane + 64] : NEGINF;

    for (int i = 0; i < 16; i++) {
        int rg = rbase + w * 16 + i;
        float xni = g_xninv[rg];
        ull m = g_mask[rg];
        float sw = xni * wv;
        size_t ro = (size_t)rg * 80;

        float c0 = dF0[ro + lane] + dF1[ro + lane];
        float c1 = dF0[ro + lane + 32] + dF1[ro + lane + 32];
        float c2 = (lane < 16) ? (dF0[ro + lane + 64] + dF1[ro + lane + 64]) : 0.f;

        float v0 = c0 * sw + bv + aI0;
        float v1 = c1 * sw + bv + aI1;
        float v2 = (lane < 16) ? (c2 * sw + bv + aI2) : NEGINF;

        float mx = fmaxf(v0, fmaxf(v1, v2));
#pragma unroll
        for (int o = 16; o; o >>= 1) mx = fmaxf(mx, __shfl_xor_sync(~0u, mx, o));

        float se = expf(v0 - mx) + expf(v1 - mx) + ((lane < 16) ? expf(v2 - mx) : 0.f);
#pragma unroll
        for (int o = 16; o; o >>= 1) se += __shfl_xor_sync(~0u, se, o);
        float lse = mx + logf(se);

        int b0 = (int)((m >> lane) & 1ull);
        int b1 = (int)((m >> (lane + 32)) & 1ull);
        int b2 = (lane == 0) ? (int)(m == 0ull) : 0;
        float sv = (b0 ? v0 : 0.f) + (b1 ? v1 : 0.f) + (b2 ? v2 : 0.f);
        int np = b0 + b1 + b2;
#pragma unroll
        for (int o = 16; o; o >>= 1) {
            sv += __shfl_xor_sync(~0u, sv, o);
            np += __shfl_xor_sync(~0u, np, o);
        }
        if (lane == 0) wl += (double)((float)np * lse - sv);
    }
    if (lane == 0) s_loss[w] = wl;
    __syncthreads();
    if (tid == 0) {
        double t = 0.0;
        for (int i = 0; i < 8; i++) t += s_loss[i];
        atomicAdd(&g_lossSum, t);
    }
}

// ---------------- finalize ----------------
__global__ void k_final(float* out) {
    __shared__ int sred[8];
    int tid = threadIdx.x;
    const int* flat = &g_cntp[0][0];
    int np = 0;
    for (int i = tid; i < 64 * 65; i += 256) np += flat[i];
#pragma unroll
    for (int o = 16; o; o >>= 1) np += __shfl_xor_sync(~0u, np, o);
    if ((tid & 31) == 0) sred[tid >> 5] = np;
    __syncthreads();
    if (tid == 0) {
        int t = 0;
        for (int i = 0; i < 8; i++) t += sred[i];
        out[0] = (float)(g_lossSum / (double)t);
    }
}

// ---------------- launcher ----------------
extern "C" void kernel_launch(void* const* d_in, const int* in_sizes, int n_in,
                              void* d_out, int out_size) {
    const float* x = nullptr;
    const int* label = nullptr;
    const float* wp = nullptr;
    const float* bp = nullptr;
    for (int i = 0; i < n_in; i++) {
        if (in_sizes[i] == B_ROWS * D_DIM) x = (const float*)d_in[i];
        else if (in_sizes[i] == B_ROWS * 64) label = (const int*)d_in[i];
        else if (in_sizes[i] == 1) {
            if (!wp) wp = (const float*)d_in[i];
            else bp = (const float*)d_in[i];
        }
    }
    k_rows<<<(B_ROWS + 7) / 8, 256>>>(x, label);
    k_meta<<<64, 256>>>();
    k_gemm1<<<dim3(2, 4, NG), 256>>>(x);
    k_anchor<<<CP, 256>>>();
    k_gemm2<<<dim3(B_ROWS / 128, 2), 256>>>(x);
    k_epi<<<B_ROWS / 128, 256>>>(wp, bp);
    k_final<<<1, 256>>>((float*)d_out);
}

// round 8
// speedup vs baseline: 1.8939x; 1.5254x over previous
#include <cuda_runtime.h>
#include <cuda_bf16.h>
#include <cstdint>

typedef unsigned long long ull;

#define B_ROWS 16384
#define D_DIM  1024
#define NC     65      // 64 labels + "no-label" extra column
#define CP     80      // padded classes
#define NG     37      // GEMM1 pair groups
#define NPAIRS 8192
#define PPAD   8224
#define PPG    222
#define NCH1   17
#define EPSV   1e-8f
#define NEGINF __int_as_float(0xff800000)

// f32x2 helpers (GEMM1 path)
#define FFMA2(acc, a, bb) asm("fma.rn.f32x2 %0, %1, %2, %0;" : "+l"(acc) : "l"(a), "l"(bb))
#define PK2(dst, lo, hi)  asm("mov.b64 %0, {%1, %2};" : "=l"(dst) : "f"(lo), "f"(hi))
#define UNPK2(lo, hi, s)  asm("mov.b64 {%0, %1}, %2;" : "=f"(lo), "=f"(hi) : "l"(s))

// warp-level tensor core helpers (base PTX, lowers to HMMA on sm_103)
#define LDSM_X4(r0, r1, r2, r3, a) \
    asm volatile("ldmatrix.sync.aligned.m8n8.x4.shared.b16 {%0,%1,%2,%3}, [%4];" \
        : "=r"(r0), "=r"(r1), "=r"(r2), "=r"(r3) : "r"(a))
#define MMA_BF16(c, a, b0, b1) \
    asm volatile("mma.sync.aligned.m16n8k16.row.col.f32.bf16.bf16.f32 " \
        "{%0,%1,%2,%3}, {%4,%5,%6,%7}, {%8,%9}, {%0,%1,%2,%3};" \
        : "+f"((c)[0]), "+f"((c)[1]), "+f"((c)[2]), "+f"((c)[3]) \
        : "r"((a)[0]), "r"((a)[1]), "r"((a)[2]), "r"((a)[3]), "r"(b0), "r"(b1))

__device__ __forceinline__ uint32_t smem_u32(const void* p) {
    uint32_t a;
    asm("{ .reg .u64 t; cvta.to.shared.u64 t, %1; cvt.u32.u64 %0, t; }" : "=r"(a) : "l"(p));
    return a;
}

// ---------------- static device scratch ----------------
__device__ ull    g_mask[B_ROWS];
__device__ float  g_xninv[B_ROWS];
__device__ int    g_cntp[64][65];
__device__ __align__(16) ull g_labp[4][PPAD][18];
__device__ float  g_part[NG][68][D_DIM];
__device__ __nv_bfloat16 g_aHi[CP][D_DIM];
__device__ __nv_bfloat16 g_aLo[CP][D_DIM];
__device__ float  g_actInf[CP];
__device__ double g_lossSum;

// ---------------- per-row label bitmask + 1/max(||x||,eps) ----------------
__global__ void k_rows(const float* __restrict__ x, const int* __restrict__ label) {
    int warp = threadIdx.x >> 5, lane = threadIdx.x & 31;
    int row = blockIdx.x * 8 + warp;
    if (row >= B_ROWS) return;

    const float4* xr = (const float4*)(x + (size_t)row * D_DIM);
    float ss = 0.f;
#pragma unroll
    for (int k = 0; k < 8; k++) {
        float4 v = xr[lane + 32 * k];
        ss += v.x * v.x + v.y * v.y + v.z * v.z + v.w * v.w;
    }
#pragma unroll
    for (int o = 16; o; o >>= 1) ss += __shfl_xor_sync(~0u, ss, o);

    const int2* lr = (const int2*)(label + (size_t)row * 64);
    int2 lv = lr[lane];
    ull part = ((ull)(lv.x != 0) << (2 * lane)) | ((ull)(lv.y != 0) << (2 * lane + 1));
#pragma unroll
    for (int o = 16; o; o >>= 1) part |= __shfl_xor_sync(~0u, part, o);

    if (lane == 0) {
        g_mask[row]  = part;
        g_xninv[row] = 1.0f / fmaxf(sqrtf(ss), EPSV);
    }
}

// ---------------- meta: counts + label pair packing + loss zero ----------------
__global__ void k_meta() {
    __shared__ ull s_m[256];
    __shared__ int s_cnt[65];
    int tid = threadIdx.x, b = blockIdx.x, lane = tid & 31;
    int row = b * 256 + tid;
    ull m = g_mask[row];
    s_m[tid] = m;
    if (tid < 65) s_cnt[tid] = 0;
    __syncthreads();

    int ca = 0, cb = 0, cz = 0;
#pragma unroll
    for (int c = 0; c < 32; c++) {
        unsigned bal = __ballot_sync(~0u, (int)((m >> c) & 1ull));
        if (lane == c) ca = __popc(bal);
    }
#pragma unroll
    for (int c = 32; c < 64; c++) {
        unsigned bal = __ballot_sync(~0u, (int)((m >> c) & 1ull));
        if (lane == c - 32) cb = __popc(bal);
    }
    {
        unsigned bal = __ballot_sync(~0u, m == 0ull);
        if (lane == 0) cz = __popc(bal);
    }
    atomicAdd(&s_cnt[lane], ca);
    atomicAdd(&s_cnt[lane + 32], cb);
    if (lane == 0) atomicAdd(&s_cnt[64], cz);

    int p = tid >> 1;
    ull m0 = s_m[2 * p], m1 = s_m[2 * p + 1];
    int pg = b * 128 + p;
#pragma unroll
    for (int qq = 0; qq < 2; qq++) {
        int q = 2 * (tid & 1) + qq;
#pragma unroll
        for (int cl = 0; cl < 18; cl++) {
            int cg = q * NCH1 + cl;
            ull v = 0ull;
            if (cl < NCH1 && cg < NC) {
                float f0, f1;
                if (cg < 64) {
                    f0 = (float)((m0 >> cg) & 1ull);
                    f1 = (float)((m1 >> cg) & 1ull);
                } else {
                    f0 = (m0 == 0ull) ? 1.f : 0.f;
                    f1 = (m1 == 0ull) ? 1.f : 0.f;
                }
                v = (ull)__float_as_uint(f0) | ((ull)__float_as_uint(f1) << 32);
            }
            g_labp[q][pg][cl] = v;
        }
    }
    __syncthreads();
    if (tid < 65) g_cntp[b][tid] = s_cnt[tid];
    if (b == 0 && tid == 0) g_lossSum = 0.0;
}

// ---------------- GEMM1: partial anchor sums (lab^T @ x), f32x2 ----------------
__global__ __launch_bounds__(256, 2) void k_gemm1(const float* __restrict__ x) {
    __shared__ __align__(16) ull s_l[32][18];

    const int tid = threadIdx.x;
    const int d0  = blockIdx.x * 512 + tid;
    const int q   = blockIdx.y;
    const int g   = blockIdx.z;
    const int pbase = g * PPG;
    const int npair = min(pbase + PPG, NPAIRS) - pbase;

    ull acc[2][17];
#pragma unroll
    for (int j = 0; j < 2; j++)
#pragma unroll
        for (int c = 0; c < 17; c++) acc[j][c] = 0ull;

    const float* xa = x + d0;
    const float* xb = x + d0 + 256;
    float f0a[2], f1a[2], f0b[2], f1b[2];
#pragma unroll
    for (int k = 0; k < 2; k++) {
        size_t r = (size_t)(2 * (pbase + k)) * D_DIM;
        f0a[k] = xa[r]; f1a[k] = xa[r + D_DIM];
        f0b[k] = xb[r]; f1b[k] = xb[r + D_DIM];
    }

    const int ntiles = (npair + 31) >> 5;
    for (int t = 0; t < ntiles; t++) {
        __syncthreads();
        {
            const float4* src = (const float4*)&g_labp[q][pbase + t * 32][0];
            float4* dst = (float4*)s_l;
            dst[tid] = src[tid];
            if (tid < 32) dst[256 + tid] = src[256 + tid];
        }
        __syncthreads();

        const int plim = min(32, npair - t * 32);
#pragma unroll 4
        for (int pp = 0; pp < plim; pp++) {
            const int idx = t * 32 + pp;
            const int sl = idx & 1;
            ull xva, xvb;
            PK2(xva, f0a[sl], f1a[sl]);
            PK2(xvb, f0b[sl], f1b[sl]);
            int pn = idx + 2;
            if (pn < npair) {
                size_t r = (size_t)(2 * (pbase + pn)) * D_DIM;
                f0a[sl] = xa[r]; f1a[sl] = xa[r + D_DIM];
                f0b[sl] = xb[r]; f1b[sl] = xb[r + D_DIM];
            }
#pragma unroll
            for (int c2 = 0; c2 < 8; c2++) {
                ulonglong2 lv = *(const ulonglong2*)&s_l[pp][2 * c2];
                FFMA2(acc[0][2 * c2],     xva, lv.x);
                FFMA2(acc[1][2 * c2],     xvb, lv.x);
                FFMA2(acc[0][2 * c2 + 1], xva, lv.y);
                FFMA2(acc[1][2 * c2 + 1], xvb, lv.y);
            }
            ull lv16 = s_l[pp][16];
            FFMA2(acc[0][16], xva, lv16);
            FFMA2(acc[1][16], xvb, lv16);
        }
    }

#pragma unroll
    for (int cl = 0; cl < 17; cl++) {
        int c = q * NCH1 + cl;
        if (c < NC) {
            float lo, hi;
            UNPK2(lo, hi, acc[0][cl]);
            g_part[g][c][d0] = lo + hi;
            UNPK2(lo, hi, acc[1][cl]);
            g_part[g][c][d0 + 256] = lo + hi;
        }
    }
}

// ---------------- reduce partials -> normalized bf16 hi/lo anchors ----------------
__global__ void k_anchor() {
    int c = blockIdx.x;
    __shared__ float sred[16];
    __shared__ float s_scale;
    __shared__ int s_count;

    if (c >= NC) {
        for (int d = threadIdx.x; d < D_DIM; d += 512) {
            g_aHi[c][d] = __float2bfloat16(0.f);
            g_aLo[c][d] = __float2bfloat16(0.f);
        }
        if (threadIdx.x == 0) g_actInf[c] = NEGINF;
        return;
    }
    if (threadIdx.x == 0) {
        int t = 0;
#pragma unroll
        for (int b = 0; b < 64; b++) t += g_cntp[b][c];
        s_count = t;
    }
    __syncthreads();
    int cnt = s_count;
    float inv = 1.0f / (float)max(cnt, 1);

    float a[2];
    float ss = 0.f;
#pragma unroll
    for (int k = 0; k < 2; k++) {
        int d = threadIdx.x + 512 * k;
        float s = 0.f;
#pragma unroll
        for (int g = 0; g < NG; g++) s += g_part[g][c][d];
        a[k] = s * inv;
        ss += a[k] * a[k];
    }
#pragma unroll
    for (int o = 16; o; o >>= 1) ss += __shfl_xor_sync(~0u, ss, o);
    if ((threadIdx.x & 31) == 0) sred[threadIdx.x >> 5] = ss;
    __syncthreads();
    if (threadIdx.x == 0) {
        float t = 0.f;
        for (int i = 0; i < 16; i++) t += sred[i];
        s_scale = 1.0f / fmaxf(sqrtf(t), EPSV);
        g_actInf[c] = (cnt > 0) ? 0.f : NEGINF;
    }
    __syncthreads();
    float sc = s_scale;
#pragma unroll
    for (int k = 0; k < 2; k++) {
        int d = threadIdx.x + 512 * k;
        float av = a[k] * sc;
        __nv_bfloat16 h = __float2bfloat16(av);
        g_aHi[c][d] = h;
        g_aLo[c][d] = __float2bfloat16(av - __bfloat162float(h));
    }
}

// ---------------- GEMM2 via warp-MMA (split-bf16, 3 passes) + fused epilogue ----------------
// 128 CTAs x 128 rows, 256 threads = 8 warps (4 row-groups x 2 col-groups).
// Warp = 32 rows (2 m16 tiles) x 40 cols (5 n8 tiles). K chunked by 64.
// Dynamic smem layout: XH 0 (16K), XL 16384 (16K), BH 32768 (96x128=12K),
//   BL 45056 (12K), LOSS 57344 (64B). Dots reuse XH/XL region ([128][81] f32).
#define SM_XH 0
#define SM_XL 16384
#define SM_BH 32768
#define SM_BL 45056
#define SM_LS 57344
#define SM_SZ 57408

__global__ __launch_bounds__(256, 1)
void k_gemm2_mma(const float* __restrict__ x,
                 const float* __restrict__ wp, const float* __restrict__ bp) {
    extern __shared__ __align__(16) char sm[];
    const uint32_t sbase = smem_u32(sm);
    const int tid = threadIdx.x, wid = tid >> 5, lane = tid & 31;
    const int wr = wid & 3, wc = wid >> 2;
    const int rbase = blockIdx.x * 128;

    float acc[2][5][4];
#pragma unroll
    for (int i = 0; i < 2; i++)
#pragma unroll
        for (int j = 0; j < 5; j++)
#pragma unroll
            for (int e = 0; e < 4; e++) acc[i][j][e] = 0.f;

    // per-lane ldmatrix address components (row within 16, k-group select)
    const int lsub = lane >> 3, lrr = lane & 7;
    const int arow_off = lrr + (lsub & 1) * 8;   // row within 16-row tile
    const int kgrp_sel = lsub >> 1;              // 0: k0-7, 1: k8-15

    for (int ch = 0; ch < 16; ch++) {
        const int d0 = ch * 64;
        __syncthreads();
        // stage x -> bf16 hi/lo, swizzled [128][64]
#pragma unroll
        for (int j = 0; j < 16; j++) {
            int idx = tid + 256 * j;
            int r = idx >> 5, k2 = idx & 31;
            float2 v = *(const float2*)(x + (size_t)(rbase + r) * D_DIM + d0 + 2 * k2);
            __nv_bfloat16 h0 = __float2bfloat16(v.x), h1 = __float2bfloat16(v.y);
            __nv_bfloat16 l0 = __float2bfloat16(v.x - __bfloat162float(h0));
            __nv_bfloat16 l1 = __float2bfloat16(v.y - __bfloat162float(h1));
            uint32_t off = (uint32_t)(r * 128 + (((k2 >> 2) ^ (r & 7)) << 4) + ((k2 & 3) << 2));
            __nv_bfloat162 hv; hv.x = h0; hv.y = h1;
            __nv_bfloat162 lv; lv.x = l0; lv.y = l1;
            *(__nv_bfloat162*)(sm + SM_XH + off) = hv;
            *(__nv_bfloat162*)(sm + SM_XL + off) = lv;
        }
        // stage anchors hi/lo [96][64] (rows 80..95 zero)
#pragma unroll
        for (int j = 0; j < 12; j++) {
            int idx = tid + 256 * j;
            int c = idx >> 5, k2 = idx & 31;
            uint32_t hw = 0, lw = 0;
            if (c < 80) {
                hw = *(const uint32_t*)&g_aHi[c][d0 + 2 * k2];
                lw = *(const uint32_t*)&g_aLo[c][d0 + 2 * k2];
            }
            uint32_t off = (uint32_t)(c * 128 + (((k2 >> 2) ^ (c & 7)) << 4) + ((k2 & 3) << 2));
            *(uint32_t*)(sm + SM_BH + off) = hw;
            *(uint32_t*)(sm + SM_BL + off) = lw;
        }
        __syncthreads();

#pragma unroll
        for (int ks = 0; ks < 4; ks++) {
            const int kc8 = 2 * ks + kgrp_sel;
            uint32_t fh[2][4], fl[2][4];
#pragma unroll
            for (int mt = 0; mt < 2; mt++) {
                int row = wr * 32 + mt * 16 + arow_off;
                uint32_t ab = (uint32_t)(row * 128 + ((kc8 ^ (row & 7)) << 4));
                LDSM_X4(fh[mt][0], fh[mt][1], fh[mt][2], fh[mt][3], sbase + SM_XH + ab);
                LDSM_X4(fl[mt][0], fl[mt][1], fl[mt][2], fl[mt][3], sbase + SM_XL + ab);
            }
            uint32_t bh[3][4], bl[3][4];
#pragma unroll
            for (int p = 0; p < 3; p++) {
                int n = wc * 40 + p * 16 + arow_off;
                uint32_t ab = (uint32_t)(n * 128 + ((kc8 ^ (n & 7)) << 4));
                LDSM_X4(bh[p][0], bh[p][1], bh[p][2], bh[p][3], sbase + SM_BH + ab);
                LDSM_X4(bl[p][0], bl[p][1], bl[p][2], bl[p][3], sbase + SM_BL + ab);
            }
#pragma unroll
            for (int mt = 0; mt < 2; mt++)
#pragma unroll
                for (int nt = 0; nt < 5; nt++) {
                    int p = nt >> 1, w2 = nt & 1;
                    MMA_BF16(acc[mt][nt], fh[mt], bh[p][w2], bh[p][2 + w2]);
                    MMA_BF16(acc[mt][nt], fh[mt], bl[p][w2], bl[p][2 + w2]);
                    MMA_BF16(acc[mt][nt], fl[mt], bh[p][w2], bh[p][2 + w2]);
                }
        }
    }

    // dots -> smem [128][81]
    __syncthreads();
    float* sd = (float*)sm;
    {
        int g = lane >> 2, t = lane & 3;
#pragma unroll
        for (int mt = 0; mt < 2; mt++)
#pragma unroll
            for (int nt = 0; nt < 5; nt++) {
                int r0 = wr * 32 + mt * 16 + g;
                int col = wc * 40 + nt * 8 + 2 * t;
                sd[r0 * 81 + col]           = acc[mt][nt][0];
                sd[r0 * 81 + col + 1]       = acc[mt][nt][1];
                sd[(r0 + 8) * 81 + col]     = acc[mt][nt][2];
                sd[(r0 + 8) * 81 + col + 1] = acc[mt][nt][3];
            }
    }
    __syncthreads();

    // fused epilogue: warp handles 16 rows; lane covers {lane, lane+32, lane+64}
    float wv = *wp, bv = *bp;
    double wl = 0.0;
    float aI0 = g_actInf[lane];
    float aI1 = g_actInf[lane + 32];
    float aI2 = (lane < 16) ? g_actInf[lane + 64] : NEGINF;

    for (int i = 0; i < 16; i++) {
        int rl = wid * 16 + i;
        int rg = rbase + rl;
        float xni = g_xninv[rg];
        ull m = g_mask[rg];
        float sw = xni * wv;

        float v0 = sd[rl * 81 + lane] * sw + bv + aI0;
        float v1 = sd[rl * 81 + lane + 32] * sw + bv + aI1;
        float v2 = (lane < 16) ? (sd[rl * 81 + lane + 64] * sw + bv + aI2) : NEGINF;

        float mx = fmaxf(v0, fmaxf(v1, v2));
#pragma unroll
        for (int o = 16; o; o >>= 1) mx = fmaxf(mx, __shfl_xor_sync(~0u, mx, o));

        float se = expf(v0 - mx) + expf(v1 - mx) + ((lane < 16) ? expf(v2 - mx) : 0.f);
#pragma unroll
        for (int o = 16; o; o >>= 1) se += __shfl_xor_sync(~0u, se, o);
        float lse = mx + logf(se);

        int b0 = (int)((m >> lane) & 1ull);
        int b1 = (int)((m >> (lane + 32)) & 1ull);
        int b2 = (lane == 0) ? (int)(m == 0ull) : 0;
        float sv = (b0 ? v0 : 0.f) + (b1 ? v1 : 0.f) + (b2 ? v2 : 0.f);
        int np = b0 + b1 + b2;
#pragma unroll
        for (int o = 16; o; o >>= 1) {
            sv += __shfl_xor_sync(~0u, sv, o);
            np += __shfl_xor_sync(~0u, np, o);
        }
        if (lane == 0) wl += (double)((float)np * lse - sv);
    }
    if (lane == 0) *(double*)(sm + SM_LS + wid * 8) = wl;
    __syncthreads();
    if (tid == 0) {
        double t = 0.0;
        for (int i = 0; i < 8; i++) t += *(double*)(sm + SM_LS + i * 8);
        atomicAdd(&g_lossSum, t);
    }
}

// ---------------- finalize ----------------
__global__ void k_final(float* out) {
    __shared__ int sred[8];
    int tid = threadIdx.x;
    const int* flat = &g_cntp[0][0];
    int np = 0;
    for (int i = tid; i < 64 * 65; i += 256) np += flat[i];
#pragma unroll
    for (int o = 16; o; o >>= 1) np += __shfl_xor_sync(~0u, np, o);
    if ((tid & 31) == 0) sred[tid >> 5] = np;
    __syncthreads();
    if (tid == 0) {
        int t = 0;
        for (int i = 0; i < 8; i++) t += sred[i];
        out[0] = (float)(g_lossSum / (double)t);
    }
}

// ---------------- launcher ----------------
extern "C" void kernel_launch(void* const* d_in, const int* in_sizes, int n_in,
                              void* d_out, int out_size) {
    const float* x = nullptr;
    const int* label = nullptr;
    const float* wp = nullptr;
    const float* bp = nullptr;
    for (int i = 0; i < n_in; i++) {
        if (in_sizes[i] == B_ROWS * D_DIM) x = (const float*)d_in[i];
        else if (in_sizes[i] == B_ROWS * 64) label = (const int*)d_in[i];
        else if (in_sizes[i] == 1) {
            if (!wp) wp = (const float*)d_in[i];
            else bp = (const float*)d_in[i];
        }
    }
    static int smem_set = 0;
    if (!smem_set) {
        cudaFuncSetAttribute(k_gemm2_mma, cudaFuncAttributeMaxDynamicSharedMemorySize, SM_SZ);
        smem_set = 1;
    }

    k_rows<<<(B_ROWS + 7) / 8, 256>>>(x, label);
    k_meta<<<64, 256>>>();
    k_gemm1<<<dim3(2, 4, NG), 256>>>(x);
    k_anchor<<<CP, 512>>>();
    k_gemm2_mma<<<B_ROWS / 128, 256, SM_SZ>>>(x, wp, bp);
    k_final<<<1, 256>>>((float*)d_out);
}

// round 9
// speedup vs baseline: 3.0078x; 1.5881x over previous
#include <cuda_runtime.h>
#include <cuda_bf16.h>
#include <cstdint>

typedef unsigned long long ull;

#define B_ROWS 16384
#define D_DIM  1024
#define NC     65      // 64 labels + "no-label" extra column
#define CP     80      // padded classes
#define NG1    16      // GEMM1 row groups (1024 rows each)
#define EPSV   1e-8f
#define NEGINF __int_as_float(0xff800000)

// warp-level tensor core helpers (base PTX, lowers to HMMA on sm_103)
#define LDSM_X4(r0, r1, r2, r3, a) \
    asm volatile("ldmatrix.sync.aligned.m8n8.x4.shared.b16 {%0,%1,%2,%3}, [%4];" \
        : "=r"(r0), "=r"(r1), "=r"(r2), "=r"(r3) : "r"(a))
#define LDSM_X4_T(r0, r1, r2, r3, a) \
    asm volatile("ldmatrix.sync.aligned.m8n8.x4.trans.shared.b16 {%0,%1,%2,%3}, [%4];" \
        : "=r"(r0), "=r"(r1), "=r"(r2), "=r"(r3) : "r"(a))
#define MMA_BF16(c, a, b0, b1) \
    asm volatile("mma.sync.aligned.m16n8k16.row.col.f32.bf16.bf16.f32 " \
        "{%0,%1,%2,%3}, {%4,%5,%6,%7}, {%8,%9}, {%0,%1,%2,%3};" \
        : "+f"((c)[0]), "+f"((c)[1]), "+f"((c)[2]), "+f"((c)[3]) \
        : "r"((a)[0]), "r"((a)[1]), "r"((a)[2]), "r"((a)[3]), "r"(b0), "r"(b1))

__device__ __forceinline__ uint32_t smem_u32(const void* p) {
    uint32_t a;
    asm("{ .reg .u64 t; cvta.to.shared.u64 t, %1; cvt.u32.u64 %0, t; }" : "=r"(a) : "l"(p));
    return a;
}

// ---------------- static device scratch ----------------
__device__ ull    g_mask[B_ROWS];
__device__ float  g_xninv[B_ROWS];
__device__ int    g_cntp[64][65];
__device__ float  g_part[NG1][CP][D_DIM];   // GEMM1 partial sums (5.2 MB)
__device__ __nv_bfloat16 g_aHi[CP][D_DIM];
__device__ __nv_bfloat16 g_aLo[CP][D_DIM];
__device__ float  g_actInf[CP];
__device__ double g_lossSum;

// ---------------- per-row label bitmask + 1/max(||x||,eps) ----------------
__global__ void k_rows(const float* __restrict__ x, const int* __restrict__ label) {
    int warp = threadIdx.x >> 5, lane = threadIdx.x & 31;
    int row = blockIdx.x * 8 + warp;
    if (row >= B_ROWS) return;

    const float4* xr = (const float4*)(x + (size_t)row * D_DIM);
    float ss = 0.f;
#pragma unroll
    for (int k = 0; k < 8; k++) {
        float4 v = xr[lane + 32 * k];
        ss += v.x * v.x + v.y * v.y + v.z * v.z + v.w * v.w;
    }
#pragma unroll
    for (int o = 16; o; o >>= 1) ss += __shfl_xor_sync(~0u, ss, o);

    const int2* lr = (const int2*)(label + (size_t)row * 64);
    int2 lv = lr[lane];
    ull part = ((ull)(lv.x != 0) << (2 * lane)) | ((ull)(lv.y != 0) << (2 * lane + 1));
#pragma unroll
    for (int o = 16; o; o >>= 1) part |= __shfl_xor_sync(~0u, part, o);

    if (lane == 0) {
        g_mask[row]  = part;
        g_xninv[row] = 1.0f / fmaxf(sqrtf(ss), EPSV);
    }
}

// ---------------- meta: per-block class counts + loss zero ----------------
__global__ void k_meta() {
    __shared__ int s_cnt[65];
    int tid = threadIdx.x, b = blockIdx.x, lane = tid & 31;
    ull m = g_mask[b * 256 + tid];
    if (tid < 65) s_cnt[tid] = 0;
    __syncthreads();

    int ca = 0, cb = 0, cz = 0;
#pragma unroll
    for (int c = 0; c < 32; c++) {
        unsigned bal = __ballot_sync(~0u, (int)((m >> c) & 1ull));
        if (lane == c) ca = __popc(bal);
    }
#pragma unroll
    for (int c = 32; c < 64; c++) {
        unsigned bal = __ballot_sync(~0u, (int)((m >> c) & 1ull));
        if (lane == c - 32) cb = __popc(bal);
    }
    {
        unsigned bal = __ballot_sync(~0u, m == 0ull);
        if (lane == 0) cz = __popc(bal);
    }
    atomicAdd(&s_cnt[lane], ca);
    atomicAdd(&s_cnt[lane + 32], cb);
    if (lane == 0) atomicAdd(&s_cnt[64], cz);
    __syncthreads();
    if (tid < 65) g_cntp[b][tid] = s_cnt[tid];
    if (b == 0 && tid == 0) g_lossSum = 0.0;
}

// ---------------- GEMM1 via warp-MMA: part[c][d] = sum_r lab[r][c] * x[r][d] ----------------
// grid (8 d-tiles, 16 row-groups), 256 threads = 8 warps (2 m-groups x 4 n-groups).
// M=96 classes (pad), N=128 d, K=1024 rows chunked by 64.
// Labels exact in bf16 -> 2 passes: lab*xh + lab*xl.
// smem: XH [64][272B] 17408, XL 17408, A [96][128B] 12288 -> 47104 B.
#define G1_XH 0
#define G1_XL 17408
#define G1_A  34816
#define G1_SZ 47104

__global__ __launch_bounds__(256, 1)
void k_gemm1_mma(const float* __restrict__ x) {
    extern __shared__ __align__(16) char sm[];
    const uint32_t sbase = smem_u32(sm);
    const int tid = threadIdx.x, wid = tid >> 5, lane = tid & 31;
    const int wm = wid & 1, wn = wid >> 1;
    const int d0 = blockIdx.x * 128;
    const int R0 = blockIdx.y * 1024;

    float acc[3][4][4];
#pragma unroll
    for (int i = 0; i < 3; i++)
#pragma unroll
        for (int j = 0; j < 4; j++)
#pragma unroll
            for (int e = 0; e < 4; e++) acc[i][j][e] = 0.f;

    // A (non-trans) lane mapping
    const int lsub = lane >> 3, lrr = lane & 7;
    const int arow = lrr + (lsub & 1) * 8;
    const int kgrp = lsub >> 1;
    // B (trans) lane mapping: M0=k0-7/n0-7, M1=k8-15/n0-7, M2=k0-7/n8-15, M3=k8-15/n8-15
    const int bk  = (lsub & 1) * 8 + lrr;
    const int bn8 = (lsub >> 1) * 8;

    const int k2 = tid & 31;          // label pair index (constant per thread)

    for (int ch = 0; ch < 16; ch++) {
        const int R = R0 + ch * 64;
        __syncthreads();
        // stage x [64 r][128 d] -> bf16 hi/lo, rows padded to 272 B
#pragma unroll
        for (int j = 0; j < 8; j++) {
            int i = tid + 256 * j;
            int r = i >> 5, q = i & 31;
            float4 v = *(const float4*)(x + (size_t)(R + r) * D_DIM + d0 + 4 * q);
            __nv_bfloat16 h0 = __float2bfloat16(v.x), h1 = __float2bfloat16(v.y);
            __nv_bfloat16 h2 = __float2bfloat16(v.z), h3 = __float2bfloat16(v.w);
            __nv_bfloat16 l0 = __float2bfloat16(v.x - __bfloat162float(h0));
            __nv_bfloat16 l1 = __float2bfloat16(v.y - __bfloat162float(h1));
            __nv_bfloat16 l2 = __float2bfloat16(v.z - __bfloat162float(h2));
            __nv_bfloat16 l3 = __float2bfloat16(v.w - __bfloat162float(h3));
            uint32_t off = (uint32_t)(r * 272 + q * 8);
            __nv_bfloat162 w0; w0.x = h0; w0.y = h1;
            __nv_bfloat162 w1; w1.x = h2; w1.y = h3;
            *(__nv_bfloat162*)(sm + G1_XH + off)     = w0;
            *(__nv_bfloat162*)(sm + G1_XH + off + 4) = w1;
            w0.x = l0; w0.y = l1; w1.x = l2; w1.y = l3;
            *(__nv_bfloat162*)(sm + G1_XL + off)     = w0;
            *(__nv_bfloat162*)(sm + G1_XL + off + 4) = w1;
        }
        // stage labels [96 c][64 r] bf16 (0/1 exact), 128B rows, swizzled
        {
            ull m0 = g_mask[R + 2 * k2], m1 = g_mask[R + 2 * k2 + 1];
            uint32_t off_base = (uint32_t)((((k2 >> 2) ^ 0) << 4) + ((k2 & 3) << 2));
#pragma unroll
            for (int j = 0; j < 12; j++) {
                int c = (tid >> 5) + 8 * j;
                uint32_t w = 0;
                if (c < 64)
                    w = (((m0 >> c) & 1ull) ? 0x3F80u : 0u) | (((m1 >> c) & 1ull) ? 0x3F800000u : 0u);
                else if (c == 64)
                    w = ((m0 == 0ull) ? 0x3F80u : 0u) | ((m1 == 0ull) ? 0x3F800000u : 0u);
                uint32_t off = (uint32_t)(c * 128 + (((k2 >> 2) ^ (c & 7)) << 4) + ((k2 & 3) << 2));
                *(uint32_t*)(sm + G1_A + off) = w;
            }
            (void)off_base;
        }
        __syncthreads();

#pragma unroll
        for (int ks = 0; ks < 4; ks++) {
            const int kc8 = 2 * ks + kgrp;
            uint32_t af[3][4];
#pragma unroll
            for (int mt = 0; mt < 3; mt++) {
                int row = wm * 48 + mt * 16 + arow;
                uint32_t ab = (uint32_t)(row * 128 + ((kc8 ^ (row & 7)) << 4));
                LDSM_X4(af[mt][0], af[mt][1], af[mt][2], af[mt][3], sbase + G1_A + ab);
            }
            uint32_t bh[2][4], bl[2][4];
#pragma unroll
            for (int t = 0; t < 2; t++) {
                uint32_t ab = (uint32_t)((ks * 16 + bk) * 272 + (wn * 32 + t * 16 + bn8) * 2);
                LDSM_X4_T(bh[t][0], bh[t][1], bh[t][2], bh[t][3], sbase + G1_XH + ab);
                LDSM_X4_T(bl[t][0], bl[t][1], bl[t][2], bl[t][3], sbase + G1_XL + ab);
            }
#pragma unroll
            for (int mt = 0; mt < 3; mt++)
#pragma unroll
                for (int nt = 0; nt < 4; nt++) {
                    int t = nt >> 1, h = nt & 1;
                    MMA_BF16(acc[mt][nt], af[mt], bh[t][2 * h], bh[t][2 * h + 1]);
                    MMA_BF16(acc[mt][nt], af[mt], bl[t][2 * h], bl[t][2 * h + 1]);
                }
        }
    }

    // store partials (only classes < NC matter)
    const int g = blockIdx.y;
    int crow = wm * 48 + (lane >> 2);
    int ccol = (lane & 3) * 2;
#pragma unroll
    for (int mt = 0; mt < 3; mt++) {
        int c0 = crow + mt * 16;
#pragma unroll
        for (int nt = 0; nt < 4; nt++) {
            int d = d0 + wn * 32 + nt * 8 + ccol;
            if (c0 < NC) {
                g_part[g][c0][d]     = acc[mt][nt][0];
                g_part[g][c0][d + 1] = acc[mt][nt][1];
            }
            if (c0 + 8 < NC) {
                g_part[g][c0 + 8][d]     = acc[mt][nt][2];
                g_part[g][c0 + 8][d + 1] = acc[mt][nt][3];
            }
        }
    }
}

// ---------------- reduce partials -> normalized bf16 hi/lo anchors ----------------
__global__ void k_anchor() {
    int c = blockIdx.x;
    __shared__ float sred[16];
    __shared__ float s_scale;
    __shared__ int s_count;

    if (c >= NC) {
        for (int d = threadIdx.x; d < D_DIM; d += 512) {
            g_aHi[c][d] = __float2bfloat16(0.f);
            g_aLo[c][d] = __float2bfloat16(0.f);
        }
        if (threadIdx.x == 0) g_actInf[c] = NEGINF;
        return;
    }
    if (threadIdx.x == 0) {
        int t = 0;
#pragma unroll
        for (int b = 0; b < 64; b++) t += g_cntp[b][c];
        s_count = t;
    }
    __syncthreads();
    int cnt = s_count;
    float inv = 1.0f / (float)max(cnt, 1);

    float a[2];
    float ss = 0.f;
#pragma unroll
    for (int k = 0; k < 2; k++) {
        int d = threadIdx.x + 512 * k;
        float s = 0.f;
#pragma unroll
        for (int g = 0; g < NG1; g++) s += g_part[g][c][d];
        a[k] = s * inv;
        ss += a[k] * a[k];
    }
#pragma unroll
    for (int o = 16; o; o >>= 1) ss += __shfl_xor_sync(~0u, ss, o);
    if ((threadIdx.x & 31) == 0) sred[threadIdx.x >> 5] = ss;
    __syncthreads();
    if (threadIdx.x == 0) {
        float t = 0.f;
        for (int i = 0; i < 16; i++) t += sred[i];
        s_scale = 1.0f / fmaxf(sqrtf(t), EPSV);
        g_actInf[c] = (cnt > 0) ? 0.f : NEGINF;
    }
    __syncthreads();
    float sc = s_scale;
#pragma unroll
    for (int k = 0; k < 2; k++) {
        int d = threadIdx.x + 512 * k;
        float av = a[k] * sc;
        __nv_bfloat16 h = __float2bfloat16(av);
        g_aHi[c][d] = h;
        g_aLo[c][d] = __float2bfloat16(av - __bfloat162float(h));
    }
}

// ---------------- GEMM2 via warp-MMA (split-bf16, 3 passes) + fused epilogue ----------------
#define SM_XH 0
#define SM_XL 16384
#define SM_BH 32768
#define SM_BL 45056
#define SM_LS 57344
#define SM_SZ 57408

__global__ __launch_bounds__(256, 1)
void k_gemm2_mma(const float* __restrict__ x,
                 const float* __restrict__ wp, const float* __restrict__ bp) {
    extern __shared__ __align__(16) char sm[];
    const uint32_t sbase = smem_u32(sm);
    const int tid = threadIdx.x, wid = tid >> 5, lane = tid & 31;
    const int wr = wid & 3, wc = wid >> 2;
    const int rbase = blockIdx.x * 128;

    float acc[2][5][4];
#pragma unroll
    for (int i = 0; i < 2; i++)
#pragma unroll
        for (int j = 0; j < 5; j++)
#pragma unroll
            for (int e = 0; e < 4; e++) acc[i][j][e] = 0.f;

    const int lsub = lane >> 3, lrr = lane & 7;
    const int arow_off = lrr + (lsub & 1) * 8;
    const int kgrp_sel = lsub >> 1;

    for (int ch = 0; ch < 16; ch++) {
        const int d0 = ch * 64;
        __syncthreads();
#pragma unroll
        for (int j = 0; j < 16; j++) {
            int idx = tid + 256 * j;
            int r = idx >> 5, ki = idx & 31;
            float2 v = *(const float2*)(x + (size_t)(rbase + r) * D_DIM + d0 + 2 * ki);
            __nv_bfloat16 h0 = __float2bfloat16(v.x), h1 = __float2bfloat16(v.y);
            __nv_bfloat16 l0 = __float2bfloat16(v.x - __bfloat162float(h0));
            __nv_bfloat16 l1 = __float2bfloat16(v.y - __bfloat162float(h1));
            uint32_t off = (uint32_t)(r * 128 + (((ki >> 2) ^ (r & 7)) << 4) + ((ki & 3) << 2));
            __nv_bfloat162 hv; hv.x = h0; hv.y = h1;
            __nv_bfloat162 lv; lv.x = l0; lv.y = l1;
            *(__nv_bfloat162*)(sm + SM_XH + off) = hv;
            *(__nv_bfloat162*)(sm + SM_XL + off) = lv;
        }
#pragma unroll
        for (int j = 0; j < 12; j++) {
            int idx = tid + 256 * j;
            int c = idx >> 5, ki = idx & 31;
            uint32_t hw = 0, lw = 0;
            if (c < 80) {
                hw = *(const uint32_t*)&g_aHi[c][d0 + 2 * ki];
                lw = *(const uint32_t*)&g_aLo[c][d0 + 2 * ki];
            }
            uint32_t off = (uint32_t)(c * 128 + (((ki >> 2) ^ (c & 7)) << 4) + ((ki & 3) << 2));
            *(uint32_t*)(sm + SM_BH + off) = hw;
            *(uint32_t*)(sm + SM_BL + off) = lw;
        }
        __syncthreads();

#pragma unroll
        for (int ks = 0; ks < 4; ks++) {
            const int kc8 = 2 * ks + kgrp_sel;
            uint32_t fh[2][4], fl[2][4];
#pragma unroll
            for (int mt = 0; mt < 2; mt++) {
                int row = wr * 32 + mt * 16 + arow_off;
                uint32_t ab = (uint32_t)(row * 128 + ((kc8 ^ (row & 7)) << 4));
                LDSM_X4(fh[mt][0], fh[mt][1], fh[mt][2], fh[mt][3], sbase + SM_XH + ab);
                LDSM_X4(fl[mt][0], fl[mt][1], fl[mt][2], fl[mt][3], sbase + SM_XL + ab);
            }
            uint32_t bh[3][4], bl[3][4];
#pragma unroll
            for (int p = 0; p < 3; p++) {
                int n = wc * 40 + p * 16 + arow_off;
                uint32_t ab = (uint32_t)(n * 128 + ((kc8 ^ (n & 7)) << 4));
                LDSM_X4(bh[p][0], bh[p][1], bh[p][2], bh[p][3], sbase + SM_BH + ab);
                LDSM_X4(bl[p][0], bl[p][1], bl[p][2], bl[p][3], sbase + SM_BL + ab);
            }
#pragma unroll
            for (int mt = 0; mt < 2; mt++)
#pragma unroll
                for (int nt = 0; nt < 5; nt++) {
                    int p = nt >> 1, w2 = nt & 1;
                    MMA_BF16(acc[mt][nt], fh[mt], bh[p][w2], bh[p][2 + w2]);
                    MMA_BF16(acc[mt][nt], fh[mt], bl[p][w2], bl[p][2 + w2]);
                    MMA_BF16(acc[mt][nt], fl[mt], bh[p][w2], bh[p][2 + w2]);
                }
        }
    }

    __syncthreads();
    float* sd = (float*)sm;
    {
        int g = lane >> 2, t = lane & 3;
#pragma unroll
        for (int mt = 0; mt < 2; mt++)
#pragma unroll
            for (int nt = 0; nt < 5; nt++) {
                int r0 = wr * 32 + mt * 16 + g;
                int col = wc * 40 + nt * 8 + 2 * t;
                sd[r0 * 81 + col]           = acc[mt][nt][0];
                sd[r0 * 81 + col + 1]       = acc[mt][nt][1];
                sd[(r0 + 8) * 81 + col]     = acc[mt][nt][2];
                sd[(r0 + 8) * 81 + col + 1] = acc[mt][nt][3];
            }
    }
    __syncthreads();

    float wv = *wp, bv = *bp;
    double wl = 0.0;
    float aI0 = g_actInf[lane];
    float aI1 = g_actInf[lane + 32];
    float aI2 = (lane < 16) ? g_actInf[lane + 64] : NEGINF;

    for (int i = 0; i < 16; i++) {
        int rl = wid * 16 + i;
        int rg = rbase + rl;
        float xni = g_xninv[rg];
        ull m = g_mask[rg];
        float sw = xni * wv;

        float v0 = sd[rl * 81 + lane] * sw + bv + aI0;
        float v1 = sd[rl * 81 + lane + 32] * sw + bv + aI1;
        float v2 = (lane < 16) ? (sd[rl * 81 + lane + 64] * sw + bv + aI2) : NEGINF;

        float mx = fmaxf(v0, fmaxf(v1, v2));
#pragma unroll
        for (int o = 16; o; o >>= 1) mx = fmaxf(mx, __shfl_xor_sync(~0u, mx, o));

        float se = expf(v0 - mx) + expf(v1 - mx) + ((lane < 16) ? expf(v2 - mx) : 0.f);
#pragma unroll
        for (int o = 16; o; o >>= 1) se += __shfl_xor_sync(~0u, se, o);
        float lse = mx + logf(se);

        int b0 = (int)((m >> lane) & 1ull);
        int b1 = (int)((m >> (lane + 32)) & 1ull);
        int b2 = (lane == 0) ? (int)(m == 0ull) : 0;
        float sv = (b0 ? v0 : 0.f) + (b1 ? v1 : 0.f) + (b2 ? v2 : 0.f);
        int np = b0 + b1 + b2;
#pragma unroll
        for (int o = 16; o; o >>= 1) {
            sv += __shfl_xor_sync(~0u, sv, o);
            np += __shfl_xor_sync(~0u, np, o);
        }
        if (lane == 0) wl += (double)((float)np * lse - sv);
    }
    if (lane == 0) *(double*)(sm + SM_LS + wid * 8) = wl;
    __syncthreads();
    if (tid == 0) {
        double t = 0.0;
        for (int i = 0; i < 8; i++) t += *(double*)(sm + SM_LS + i * 8);
        atomicAdd(&g_lossSum, t);
    }
}

// ---------------- finalize ----------------
__global__ void k_final(float* out) {
    __shared__ int sred[8];
    int tid = threadIdx.x;
    const int* flat = &g_cntp[0][0];
    int np = 0;
    for (int i = tid; i < 64 * 65; i += 256) np += flat[i];
#pragma unroll
    for (int o = 16; o; o >>= 1) np += __shfl_xor_sync(~0u, np, o);
    if ((tid & 31) == 0) sred[tid >> 5] = np;
    __syncthreads();
    if (tid == 0) {
        int t = 0;
        for (int i = 0; i < 8; i++) t += sred[i];
        out[0] = (float)(g_lossSum / (double)t);
    }
}

// ---------------- launcher ----------------
extern "C" void kernel_launch(void* const* d_in, const int* in_sizes, int n_in,
                              void* d_out, int out_size) {
    const float* x = nullptr;
    const int* label = nullptr;
    const float* wp = nullptr;
    const float* bp = nullptr;
    for (int i = 0; i < n_in; i++) {
        if (in_sizes[i] == B_ROWS * D_DIM) x = (const float*)d_in[i];
        else if (in_sizes[i] == B_ROWS * 64) label = (const int*)d_in[i];
        else if (in_sizes[i] == 1) {
            if (!wp) wp = (const float*)d_in[i];
            else bp = (const float*)d_in[i];
        }
    }
    static int smem_set = 0;
    if (!smem_set) {
        cudaFuncSetAttribute(k_gemm2_mma, cudaFuncAttributeMaxDynamicSharedMemorySize, SM_SZ);
        cudaFuncSetAttribute(k_gemm1_mma, cudaFuncAttributeMaxDynamicSharedMemorySize, G1_SZ);
        smem_set = 1;
    }

    k_rows<<<(B_ROWS + 7) / 8, 256>>>(x, label);
    k_meta<<<64, 256>>>();
    k_gemm1_mma<<<dim3(8, NG1), 256, G1_SZ>>>(x);
    k_anchor<<<CP, 512>>>();
    k_gemm2_mma<<<B_ROWS / 128, 256, SM_SZ>>>(x, wp, bp);
    k_final<<<1, 256>>>((float*)d_out);
}